// round 14
// baseline (speedup 1.0000x reference)
#include <cuda_runtime.h>
#include <cuda_bf16.h>
#include <cstdint>

// ---------------------------------------------------------------------------
// Problem constants
// ---------------------------------------------------------------------------
#define BATCH   64
#define SEQ     2048
#define CIN     32
#define WIN     20
#define DIN     (WIN * CIN)      // 640
#define DP      (DIN / 2)        // 320
#define HID     128
#define G4      (4 * HID)        // 512
#define L_OUT   (SEQ - WIN)      // 2028
#define XT      2032             // padded time stride for g_xpre
#define LBL     48

// ---------------------------------------------------------------------------
// Scratch (static __device__ arrays; no cudaMalloc allowed)
// ---------------------------------------------------------------------------
__device__ float g_wc[DIN * G4];                       // combined proj->ih0 weight [k][g], tf32-rounded
__device__ float g_bias0[G4];
__device__ float g_xpre[(size_t)BATCH * G4 * XT];      // preactivations, [b][g][t] (t-major)
__device__ float g_hseq[(size_t)BATCH * L_OUT * HID];  // per-step hidden outputs [b][t][h]

// ---------------------------------------------------------------------------
// Packed fp32x2 helpers (scan only)
// ---------------------------------------------------------------------------
__device__ __forceinline__ unsigned long long pk2(float x, float y) {
    unsigned long long r;
    asm("mov.b64 %0, {%1, %2};" : "=l"(r) : "f"(x), "f"(y));
    return r;
}
__device__ __forceinline__ float2 unpk2(unsigned long long v) {
    float2 r;
    asm("mov.b64 {%0, %1}, %2;" : "=f"(r.x), "=f"(r.y) : "l"(v));
    return r;
}
__device__ __forceinline__ void fma2(unsigned long long& d, unsigned long long a,
                                     unsigned long long b) {
    asm("fma.rn.f32x2 %0, %1, %2, %3;" : "=l"(d) : "l"(a), "l"(b), "l"(d));
}
__device__ __forceinline__ unsigned long long add2(unsigned long long a,
                                                   unsigned long long b) {
    unsigned long long r;
    asm("add.rn.f32x2 %0, %1, %2;" : "=l"(r) : "l"(a), "l"(b));
    return r;
}

// ---------------------------------------------------------------------------
// tf32 helpers
// ---------------------------------------------------------------------------
__device__ __forceinline__ float to_tf32(float x) {
    unsigned u;
    asm("cvt.rna.tf32.f32 %0, %1;" : "=r"(u) : "f"(x));
    return __uint_as_float(u);
}
// D(16x8,f32) += A(16x8 tf32, row) * B(8x8 tf32, col)
__device__ __forceinline__ void mma_tf32(float* d, const unsigned* a, const unsigned* b) {
    asm volatile(
        "mma.sync.aligned.m16n8k8.row.col.f32.tf32.tf32.f32 "
        "{%0,%1,%2,%3}, {%4,%5,%6,%7}, {%8,%9}, {%0,%1,%2,%3};"
        : "+f"(d[0]), "+f"(d[1]), "+f"(d[2]), "+f"(d[3])
        : "r"(a[0]), "r"(a[1]), "r"(a[2]), "r"(a[3]), "r"(b[0]), "r"(b[1]));
}

// ---------------------------------------------------------------------------
// Cluster / mbarrier helpers
// ---------------------------------------------------------------------------
__device__ __forceinline__ unsigned smem_u32(const void* p) {
    return (unsigned)__cvta_generic_to_shared(p);
}
__device__ __forceinline__ unsigned mapa_rank(unsigned addr, unsigned rank) {
    unsigned r;
    asm("mapa.shared::cluster.u32 %0, %1, %2;" : "=r"(r) : "r"(addr), "r"(rank));
    return r;
}
__device__ __forceinline__ void mbar_init(unsigned addr, unsigned cnt) {
    asm volatile("mbarrier.init.shared.b64 [%0], %1;" :: "r"(addr), "r"(cnt) : "memory");
}
__device__ __forceinline__ void mbar_expect_tx(unsigned addr, unsigned bytes) {
    asm volatile("mbarrier.arrive.expect_tx.shared.b64 _, [%0], %1;"
                 :: "r"(addr), "r"(bytes) : "memory");
}
// Packed remote SMEM store (8 bytes) with mbarrier tx-completion.
__device__ __forceinline__ void st_async_f32x2(unsigned raddr, float x, float y,
                                               unsigned rmbar) {
    unsigned long long v = pk2(x, y);   // little-endian: x at raddr, y at raddr+4
    asm volatile(
        "st.async.shared::cluster.mbarrier::complete_tx::bytes.b64 [%0], %1, [%2];"
        :: "r"(raddr), "l"(v), "r"(rmbar) : "memory");
}
// Single non-blocking probe; returns 1 if phase complete (carries acquire).
__device__ __forceinline__ unsigned mbar_try_once(unsigned addr, unsigned parity) {
    unsigned done;
    asm volatile(
        "{\n\t"
        ".reg .pred p;\n\t"
        "mbarrier.try_wait.parity.acquire.cluster.shared::cta.b64 p, [%1], %2;\n\t"
        "selp.b32 %0, 1, 0, p;\n\t"
        "}"
        : "=r"(done) : "r"(addr), "r"(parity) : "memory");
    return done;
}
__device__ __forceinline__ void mbar_wait_cluster(unsigned addr, unsigned parity) {
    asm volatile(
        "{\n\t"
        ".reg .pred P1;\n\t"
        "WAIT_%=:\n\t"
        "mbarrier.try_wait.parity.acquire.cluster.shared::cta.b64 P1, [%0], %1, 0x989680;\n\t"
        "@P1 bra.uni DONE_%=;\n\t"
        "bra.uni WAIT_%=;\n\t"
        "DONE_%=:\n\t"
        "}"
        :: "r"(addr), "r"(parity) : "memory");
}
__device__ __forceinline__ void cluster_barrier() {
    asm volatile("barrier.cluster.arrive.aligned;" ::: "memory");
    asm volatile("barrier.cluster.wait.aligned;" ::: "memory");
}

// ---------------------------------------------------------------------------
// Fast activations: HW tanh unit (sm_75+), sigmoid via tanh identity.
// ---------------------------------------------------------------------------
__device__ __forceinline__ float tanhf_fast(float x) {
    float y;
    asm("tanh.approx.f32 %0, %1;" : "=f"(y) : "f"(x));
    return y;
}

// ---------------------------------------------------------------------------
// Kernel 1: fold projection into layer-0 input weight (tf32-rounded output).
// ---------------------------------------------------------------------------
__global__ void combine_kernel(const float* __restrict__ proj_w,
                               const float* __restrict__ w_ih0) {
    __shared__ float sPW[32][32];
    __shared__ float sWI[32][33];
    int tx = threadIdx.x, ty = threadIdx.y;
    int d0 = blockIdx.x * 32, g0 = blockIdx.y * 32;
    float acc = 0.f;
    for (int p0 = 0; p0 < DP; p0 += 32) {
        sPW[ty][tx] = proj_w[(size_t)(p0 + ty) * DIN + d0 + tx];
        sWI[ty][tx] = w_ih0[(size_t)(g0 + ty) * DP + p0 + tx];
        __syncthreads();
#pragma unroll
        for (int p = 0; p < 32; p++) acc += sPW[p][tx] * sWI[ty][p];
        __syncthreads();
    }
    g_wc[(size_t)(d0 + tx) * G4 + g0 + ty] = to_tf32(acc);
}

__global__ void bias0_kernel(const float* __restrict__ proj_b,
                             const float* __restrict__ w_ih0,
                             const float* __restrict__ b_ih0,
                             const float* __restrict__ b_hh0) {
    int gidx = threadIdx.x;
    float acc = b_ih0[gidx] + b_hh0[gidx];
    const float* wr = w_ih0 + (size_t)gidx * DP;
    for (int p = 0; p < DP; p++) acc += proj_b[p] * wr[p];
    g_bias0[gidx] = acc;
}

// ---------------------------------------------------------------------------
// Kernel 2: layer-0 preactivations via tf32 tensor cores (R11, unchanged).
// ---------------------------------------------------------------------------
#define APAD0 68
#define BPAD0 72
__global__ void __launch_bounds__(256)
xpre0_kernel(const float* __restrict__ in) {
    __shared__ __align__(16) float sIn[128 * 32 + DIN];
    __shared__ __align__(16) float buf[128 * APAD0 + 64 * BPAD0];
    float* sAp = buf;
    float* sWp = buf + 128 * APAD0;
    float* sT  = buf;

    int tid  = threadIdx.x;
    int wid  = tid >> 5, lane = tid & 31;
    int gid  = lane >> 2, tig = lane & 3;
    int wm   = wid >> 1, wn = wid & 1;
    int t0 = blockIdx.x * 128;
    int n0 = blockIdx.y * 64;
    int b  = blockIdx.z;

    const float* inb = in + (size_t)b * SEQ * CIN;
    int base = t0 * CIN;
    for (int i = tid; i < 128 * 32 + DIN; i += 256) {
        int gi = base + i;
        sIn[i] = (gi < SEQ * CIN) ? to_tf32(inb[gi]) : 0.f;
    }

    float acc[2][4][4];
#pragma unroll
    for (int mi = 0; mi < 2; mi++)
#pragma unroll
        for (int ni = 0; ni < 4; ni++)
#pragma unroll
            for (int e = 0; e < 4; e++) acc[mi][ni][e] = 0.f;

    __syncthreads();

    for (int kc = 0; kc < 10; kc++) {
#pragma unroll
        for (int r = 0; r < 8; r++) {
            int j = tid + r * 256;
            int t = j >> 4, k4 = (j & 15) << 2;
            *(float4*)&sAp[t * APAD0 + k4] = *(const float4*)&sIn[t * 32 + kc * 64 + k4];
        }
#pragma unroll
        for (int r = 0; r < 4; r++) {
            int j = tid + r * 256;
            int k = j >> 4, g4 = (j & 15) << 2;
            *(float4*)&sWp[k * BPAD0 + g4] =
                *(const float4*)&g_wc[(size_t)(kc * 64 + k) * G4 + n0 + g4];
        }
        __syncthreads();

#pragma unroll
        for (int ki = 0; ki < 8; ki++) {
            unsigned afr[2][4];
#pragma unroll
            for (int mi = 0; mi < 2; mi++) {
                const float* ar = sAp + (wm * 32 + mi * 16 + gid) * APAD0 + ki * 8 + tig;
                afr[mi][0] = __float_as_uint(ar[0]);
                afr[mi][1] = __float_as_uint(ar[8 * APAD0]);
                afr[mi][2] = __float_as_uint(ar[4]);
                afr[mi][3] = __float_as_uint(ar[8 * APAD0 + 4]);
            }
            unsigned bfr[4][2];
#pragma unroll
            for (int ni = 0; ni < 4; ni++) {
                const float* br = sWp + (ki * 8 + tig) * BPAD0 + wn * 32 + ni * 8 + gid;
                bfr[ni][0] = __float_as_uint(br[0]);
                bfr[ni][1] = __float_as_uint(br[4 * BPAD0]);
            }
#pragma unroll
            for (int mi = 0; mi < 2; mi++)
#pragma unroll
                for (int ni = 0; ni < 4; ni++)
                    mma_tf32(acc[mi][ni], afr[mi], bfr[ni]);
        }
        __syncthreads();
    }

#pragma unroll
    for (int mi = 0; mi < 2; mi++)
#pragma unroll
        for (int ni = 0; ni < 4; ni++) {
            int tl = wm * 32 + mi * 16 + gid;
            int gl = wn * 32 + ni * 8 + tig * 2;
            sT[gl * 132 + tl]           = acc[mi][ni][0];
            sT[(gl + 1) * 132 + tl]     = acc[mi][ni][1];
            sT[gl * 132 + tl + 8]       = acc[mi][ni][2];
            sT[(gl + 1) * 132 + tl + 8] = acc[mi][ni][3];
        }
    __syncthreads();
#pragma unroll
    for (int r = 0; r < 8; r++) {
        int j = tid + r * 256;
        int g = j >> 5, t4 = (j & 31) << 2;
        if (t0 + t4 + 4 <= XT) {
            float4 v = *(float4*)&sT[g * 132 + t4];
            float bv = g_bias0[n0 + g];
            v.x += bv; v.y += bv; v.z += bv; v.w += bv;
            *(float4*)&g_xpre[((size_t)b * G4 + n0 + g) * XT + t0 + t4] = v;
        }
    }
}

// ---------------------------------------------------------------------------
// Kernel 3: input preactivations for layers 1..3 via tf32 (R11, unchanged).
// ---------------------------------------------------------------------------
#define APAD1 132
#define BPAD1 72
__global__ void __launch_bounds__(256)
gemm_ih_kernel(const float* __restrict__ w_ih,
               const float* __restrict__ b_ih,
               const float* __restrict__ b_hh) {
    __shared__ __align__(16) float buf[64 * APAD1 + 128 * BPAD1];
    float* sA = buf;
    float* sB = buf + 64 * APAD1;
    float* sT = buf;

    int tid  = threadIdx.x;
    int wid  = tid >> 5, lane = tid & 31;
    int gid  = lane >> 2, tig = lane & 3;
    int wm   = wid & 1, wn = wid >> 1;
    int t0 = blockIdx.x * 64;
    int n0 = blockIdx.y * 64;
    int b  = blockIdx.z;

#pragma unroll
    for (int r = 0; r < 8; r++) {
        int j = tid + r * 256;
        int t = j >> 5, k4 = (j & 31) << 2;
        float4 v = make_float4(0.f, 0.f, 0.f, 0.f);
        if (t0 + t < L_OUT)
            v = *(const float4*)&g_hseq[((size_t)b * L_OUT + t0 + t) * HID + k4];
        v.x = to_tf32(v.x); v.y = to_tf32(v.y); v.z = to_tf32(v.z); v.w = to_tf32(v.w);
        *(float4*)&sA[t * APAD1 + k4] = v;
    }
#pragma unroll
    for (int r = 0; r < 8; r++) {
        int j = tid + r * 256;
        int g = j & 63, kg = j >> 6;
        int k4 = kg << 2;
        float4 v = *(const float4*)&w_ih[(size_t)(n0 + g) * HID + k4];
        sB[(k4 + 0) * BPAD1 + g] = to_tf32(v.x);
        sB[(k4 + 1) * BPAD1 + g] = to_tf32(v.y);
        sB[(k4 + 2) * BPAD1 + g] = to_tf32(v.z);
        sB[(k4 + 3) * BPAD1 + g] = to_tf32(v.w);
    }
    __syncthreads();

    float acc[2][2][4];
#pragma unroll
    for (int mi = 0; mi < 2; mi++)
#pragma unroll
        for (int ni = 0; ni < 2; ni++)
#pragma unroll
            for (int e = 0; e < 4; e++) acc[mi][ni][e] = 0.f;

#pragma unroll
    for (int ki = 0; ki < 16; ki++) {
        unsigned afr[2][4];
#pragma unroll
        for (int mi = 0; mi < 2; mi++) {
            const float* ar = sA + (wm * 32 + mi * 16 + gid) * APAD1 + ki * 8 + tig;
            afr[mi][0] = __float_as_uint(ar[0]);
            afr[mi][1] = __float_as_uint(ar[8 * APAD1]);
            afr[mi][2] = __float_as_uint(ar[4]);
            afr[mi][3] = __float_as_uint(ar[8 * APAD1 + 4]);
        }
        unsigned bfr[2][2];
#pragma unroll
        for (int ni = 0; ni < 2; ni++) {
            const float* br = sB + (ki * 8 + tig) * BPAD1 + wn * 16 + ni * 8 + gid;
            bfr[ni][0] = __float_as_uint(br[0]);
            bfr[ni][1] = __float_as_uint(br[4 * BPAD1]);
        }
#pragma unroll
        for (int mi = 0; mi < 2; mi++)
#pragma unroll
            for (int ni = 0; ni < 2; ni++)
                mma_tf32(acc[mi][ni], afr[mi], bfr[ni]);
    }
    __syncthreads();

#pragma unroll
    for (int mi = 0; mi < 2; mi++)
#pragma unroll
        for (int ni = 0; ni < 2; ni++) {
            int tl = wm * 32 + mi * 16 + gid;
            int gl = wn * 16 + ni * 8 + tig * 2;
            sT[gl * 68 + tl]           = acc[mi][ni][0];
            sT[(gl + 1) * 68 + tl]     = acc[mi][ni][1];
            sT[gl * 68 + tl + 8]       = acc[mi][ni][2];
            sT[(gl + 1) * 68 + tl + 8] = acc[mi][ni][3];
        }
    __syncthreads();
#pragma unroll
    for (int r = 0; r < 4; r++) {
        int j = tid + r * 256;
        int g = j >> 4, t4 = (j & 15) << 2;
        if (t0 + t4 + 4 <= XT) {
            float4 v = *(float4*)&sT[g * 68 + t4];
            float bv = b_ih[n0 + g] + b_hh[n0 + g];
            v.x += bv; v.y += bv; v.z += bv; v.w += bv;
            *(float4*)&g_xpre[((size_t)b * G4 + n0 + g) * XT + t0 + t4] = v;
        }
    }
}

// ---------------------------------------------------------------------------
// Kernel 4: recurrent scan — R12 structure with three dependency-chain cuts:
//  (1) EARLY non-blocking mbarrier probe before the own-half dot: the ~90cyc
//      TRYWAIT fast-path latency overlaps the dot; the blocking loop runs
//      only if the peer data hasn't landed yet (warp-uniform predicate).
//      Parity-aliasing safe: peer can never be 2 phases ahead on one bar
//      (its next-phase stores require its wait on OUR current-step stores).
//  (2) xp folded into accumulator init (deletes the final dependent add).
//  (3) packed f32x2 reduction tree (3 add2 + 1 unpack + 1 add vs 4 unpacks
//      + 7 scalar adds).
// Transport/parity protocol bitwise = R12 (proven).
// ---------------------------------------------------------------------------
__global__ void __cluster_dims__(2, 1, 1) __launch_bounds__(256, 1)
scan_kernel(const float* __restrict__ w_hh) {
    __shared__ __align__(16) float hbuf[2][64];
    __shared__ __align__(16) float land[2][64];
    __shared__ __align__(8) unsigned long long mbars[2];

    int tid  = threadIdx.x;
    int rank = blockIdx.x & 1;
    int b    = blockIdx.x >> 1;
    int gate = tid & 3;
    int ul   = tid >> 2;
    int ug   = rank * 64 + ul;
    int row  = gate * HID + ug;
    int kown  = rank * 64;
    int kpeer = (rank ^ 1) * 64;

    unsigned long long wown[32], wpeer[32];
    {
        const ulonglong2* wr = (const ulonglong2*)(w_hh + (size_t)row * HID + kown);
#pragma unroll
        for (int k = 0; k < 16; k++) {
            ulonglong2 u = wr[k];
            wown[2 * k]     = u.x;
            wown[2 * k + 1] = u.y;
        }
        const ulonglong2* wp = (const ulonglong2*)(w_hh + (size_t)row * HID + kpeer);
#pragma unroll
        for (int k = 0; k < 16; k++) {
            ulonglong2 u = wp[k];
            wpeer[2 * k]     = u.x;
            wpeer[2 * k + 1] = u.y;
        }
    }

    if (tid < 64) {
        hbuf[0][tid] = 0.f; hbuf[1][tid] = 0.f;
        land[0][tid] = 0.f; land[1][tid] = 0.f;
    }
    unsigned bar0 = smem_u32(&mbars[0]);
    unsigned bar1 = smem_u32(&mbars[1]);
    if (tid == 0) { mbar_init(bar0, 1); mbar_init(bar1, 1); }
    __syncthreads();
    cluster_barrier();

    unsigned peer = rank ^ 1;
    unsigned peer_l0 = mapa_rank(smem_u32(&land[0][0]), peer) + (unsigned)ul * 4u;
    unsigned peer_l1 = mapa_rank(smem_u32(&land[1][0]), peer) + (unsigned)ul * 4u;
    unsigned peer_b0 = mapa_rank(bar0, peer);
    unsigned peer_b1 = mapa_rank(bar1, peer);

    float c = 0.f;
    const size_t hrow = (size_t)b * L_OUT;
    const float* xrow_p = g_xpre + ((size_t)b * G4 + row) * XT;

    // activation via tanh unit: act = A*tanh(B*pre) + C
    const float A_ = (gate == 2) ? 1.f : 0.5f;
    const float B_ = (gate == 2) ? 1.f : 0.5f;
    const float C_ = (gate == 2) ? 0.f : 0.5f;
    const bool  tail   = (gate == 0);
    const bool  sender = tail && ((ul & 1) == 0);

    float4 xcur = *(const float4*)(xrow_p);

    for (int t4 = 0; t4 < L_OUT; t4 += 4) {
        float4 xnxt = *(const float4*)(xrow_p + t4 + 4);

#pragma unroll
        for (int s = 0; s < 4; s++) {
            int t = t4 + s;
            float xp = (s == 0) ? xcur.x : (s == 1) ? xcur.y : (s == 2) ? xcur.z : xcur.w;

            if (tid == 0 && t + 1 < L_OUT)
                mbar_expect_tx((t & 1) ? bar1 : bar0, 256);

            // early non-blocking probe; latency overlaps the own-half dot
            unsigned pbar = 0, ppar = 0, done = 1;
            if (t > 0) {
                int pv = t - 1;
                pbar = (pv & 1) ? bar1 : bar0;
                ppar = (unsigned)((pv >> 1) & 1);
                done = mbar_try_once(pbar, ppar);
            }

            // own half (acc0 seeded with xp — folds the final add)
            unsigned long long a0 = pk2(xp, 0.f), a1 = pk2(0.f, 0.f);
            unsigned long long a2 = pk2(0.f, 0.f), a3 = pk2(0.f, 0.f);
            {
                const ulonglong2* h2 = (const ulonglong2*)hbuf[(t + 1) & 1];
#pragma unroll
                for (int k = 0; k < 8; k++) {
                    ulonglong2 u = h2[2 * k];
                    ulonglong2 v = h2[2 * k + 1];
                    fma2(a0, wown[4 * k],     u.x);
                    fma2(a1, wown[4 * k + 1], u.y);
                    fma2(a2, wown[4 * k + 2], v.x);
                    fma2(a3, wown[4 * k + 3], v.y);
                }
            }

            if (!done) mbar_wait_cluster(pbar, ppar);   // fallback (rare)

            // peer half from landing buffer
            {
                const ulonglong2* h2 = (const ulonglong2*)land[(t + 1) & 1];
#pragma unroll
                for (int k = 0; k < 8; k++) {
                    ulonglong2 u = h2[2 * k];
                    ulonglong2 v = h2[2 * k + 1];
                    fma2(a0, wpeer[4 * k],     u.x);
                    fma2(a1, wpeer[4 * k + 1], u.y);
                    fma2(a2, wpeer[4 * k + 2], v.x);
                    fma2(a3, wpeer[4 * k + 3], v.y);
                }
            }

            // packed reduction tree
            float2 q = unpk2(add2(add2(a0, a1), add2(a2, a3)));
            float pre = q.x + q.y;
            float act = fmaf(A_, tanhf_fast(B_ * pre), C_);

            float fv = __shfl_down_sync(0xffffffffu, act, 1);
            float gv = __shfl_down_sync(0xffffffffu, act, 2);
            float ov = __shfl_down_sync(0xffffffffu, act, 3);

            float h = 0.f;
            if (tail) {
                c = fmaf(fv, c, act * gv);        // act == i
                h = ov * tanhf_fast(c);
            }
            float hp = __shfl_down_sync(0xffffffffu, h, 4);
            if (tail) {
                if (sender && t + 1 < L_OUT)
                    st_async_f32x2((t & 1) ? peer_l1 : peer_l0, h, hp,
                                   (t & 1) ? peer_b1 : peer_b0);
                hbuf[t & 1][ul] = h;
                g_hseq[(hrow + t) * HID + ug] = h;
            }
            __syncthreads();
        }
        xcur = xnxt;
    }
    cluster_barrier();
}

// ---------------------------------------------------------------------------
// Kernel 5: readout.
// ---------------------------------------------------------------------------
__global__ void out_kernel(const float* __restrict__ out_w,
                           const float* __restrict__ out_b,
                           float* __restrict__ out) {
    __shared__ float h[HID];
    int b = blockIdx.x;
    if (threadIdx.x < HID)
        h[threadIdx.x] = g_hseq[((size_t)b * L_OUT + (L_OUT - 1)) * HID + threadIdx.x];
    __syncthreads();
    if (threadIdx.x < LBL) {
        float acc = out_b[threadIdx.x];
        const float* wr = out_w + (size_t)threadIdx.x * HID;
#pragma unroll 8
        for (int k = 0; k < HID; k++) acc += wr[k] * h[k];
        out[(size_t)b * LBL + threadIdx.x] = acc;
    }
}

// ---------------------------------------------------------------------------
// Launch
// ---------------------------------------------------------------------------
extern "C" void kernel_launch(void* const* d_in, const int* in_sizes, int n_in,
                              void* d_out, int out_size) {
    const float* inputs    = (const float*)d_in[0];
    const float* proj_w    = (const float*)d_in[4];
    const float* proj_b    = (const float*)d_in[5];
    const float* w_ih0     = (const float*)d_in[6];
    const float* w_hh0     = (const float*)d_in[7];
    const float* b_ih0     = (const float*)d_in[8];
    const float* b_hh0     = (const float*)d_in[9];
    const float* w_ih_rest = (const float*)d_in[10];
    const float* w_hh_rest = (const float*)d_in[11];
    const float* b_ih_rest = (const float*)d_in[12];
    const float* b_hh_rest = (const float*)d_in[13];
    const float* out_w     = (const float*)d_in[14];
    const float* out_b     = (const float*)d_in[15];
    float* out = (float*)d_out;

    combine_kernel<<<dim3(DIN / 32, G4 / 32), dim3(32, 32)>>>(proj_w, w_ih0);
    bias0_kernel<<<1, G4>>>(proj_b, w_ih0, b_ih0, b_hh0);

    xpre0_kernel<<<dim3((L_OUT + 127) / 128, G4 / 64, BATCH), 256>>>(inputs);

    scan_kernel<<<BATCH * 2, 256>>>(w_hh0);

    for (int l = 0; l < 3; l++) {
        gemm_ih_kernel<<<dim3((L_OUT + 63) / 64, G4 / 64, BATCH), 256>>>(
            w_ih_rest + (size_t)l * G4 * HID,
            b_ih_rest + (size_t)l * G4,
            b_hh_rest + (size_t)l * G4);
        scan_kernel<<<BATCH * 2, 256>>>(w_hh_rest + (size_t)l * G4 * HID);
    }

    out_kernel<<<BATCH, 128>>>(out_w, out_b, out);
}

// round 15
// speedup vs baseline: 1.0428x; 1.0428x over previous
#include <cuda_runtime.h>
#include <cuda_bf16.h>
#include <cstdint>

// ---------------------------------------------------------------------------
// Problem constants
// ---------------------------------------------------------------------------
#define BATCH   64
#define SEQ     2048
#define CIN     32
#define WIN     20
#define DIN     (WIN * CIN)      // 640
#define DP      (DIN / 2)        // 320
#define HID     128
#define G4      (4 * HID)        // 512
#define L_OUT   (SEQ - WIN)      // 2028
#define XT      2032             // padded time stride for g_xpre
#define LBL     48

// ---------------------------------------------------------------------------
// Scratch (static __device__ arrays; no cudaMalloc allowed)
// ---------------------------------------------------------------------------
__device__ float g_wc[DIN * G4];                       // combined proj->ih0 weight [k][g], tf32-rounded
__device__ float g_bias0[G4];
__device__ float g_xpre[(size_t)BATCH * G4 * XT];      // preactivations, [b][g][t] (t-major)
__device__ float g_hseq[(size_t)BATCH * L_OUT * HID];  // per-step hidden outputs [b][t][h]

// ---------------------------------------------------------------------------
// Packed fp32x2 helpers (scan only)
// ---------------------------------------------------------------------------
__device__ __forceinline__ unsigned long long pk2(float x, float y) {
    unsigned long long r;
    asm("mov.b64 %0, {%1, %2};" : "=l"(r) : "f"(x), "f"(y));
    return r;
}
__device__ __forceinline__ float2 unpk2(unsigned long long v) {
    float2 r;
    asm("mov.b64 {%0, %1}, %2;" : "=f"(r.x), "=f"(r.y) : "l"(v));
    return r;
}
__device__ __forceinline__ void fma2(unsigned long long& d, unsigned long long a,
                                     unsigned long long b) {
    asm("fma.rn.f32x2 %0, %1, %2, %3;" : "=l"(d) : "l"(a), "l"(b), "l"(d));
}
__device__ __forceinline__ unsigned long long add2(unsigned long long a,
                                                   unsigned long long b) {
    unsigned long long r;
    asm("add.rn.f32x2 %0, %1, %2;" : "=l"(r) : "l"(a), "l"(b));
    return r;
}

// ---------------------------------------------------------------------------
// tf32 helpers
// ---------------------------------------------------------------------------
__device__ __forceinline__ float to_tf32(float x) {
    unsigned u;
    asm("cvt.rna.tf32.f32 %0, %1;" : "=r"(u) : "f"(x));
    return __uint_as_float(u);
}
// D(16x8,f32) += A(16x8 tf32, row) * B(8x8 tf32, col)
__device__ __forceinline__ void mma_tf32(float* d, const unsigned* a, const unsigned* b) {
    asm volatile(
        "mma.sync.aligned.m16n8k8.row.col.f32.tf32.tf32.f32 "
        "{%0,%1,%2,%3}, {%4,%5,%6,%7}, {%8,%9}, {%0,%1,%2,%3};"
        : "+f"(d[0]), "+f"(d[1]), "+f"(d[2]), "+f"(d[3])
        : "r"(a[0]), "r"(a[1]), "r"(a[2]), "r"(a[3]), "r"(b[0]), "r"(b[1]));
}

// ---------------------------------------------------------------------------
// Cluster / mbarrier helpers
// ---------------------------------------------------------------------------
__device__ __forceinline__ unsigned smem_u32(const void* p) {
    return (unsigned)__cvta_generic_to_shared(p);
}
__device__ __forceinline__ unsigned mapa_rank(unsigned addr, unsigned rank) {
    unsigned r;
    asm("mapa.shared::cluster.u32 %0, %1, %2;" : "=r"(r) : "r"(addr), "r"(rank));
    return r;
}
__device__ __forceinline__ void mbar_init(unsigned addr, unsigned cnt) {
    asm volatile("mbarrier.init.shared.b64 [%0], %1;" :: "r"(addr), "r"(cnt) : "memory");
}
__device__ __forceinline__ void mbar_expect_tx(unsigned addr, unsigned bytes) {
    asm volatile("mbarrier.arrive.expect_tx.shared.b64 _, [%0], %1;"
                 :: "r"(addr), "r"(bytes) : "memory");
}
// Packed remote SMEM store (8 bytes) with mbarrier tx-completion.
__device__ __forceinline__ void st_async_f32x2(unsigned raddr, float x, float y,
                                               unsigned rmbar) {
    unsigned long long v = pk2(x, y);   // little-endian: x at raddr, y at raddr+4
    asm volatile(
        "st.async.shared::cluster.mbarrier::complete_tx::bytes.b64 [%0], %1, [%2];"
        :: "r"(raddr), "l"(v), "r"(rmbar) : "memory");
}
__device__ __forceinline__ void mbar_wait_cluster(unsigned addr, unsigned parity) {
    asm volatile(
        "{\n\t"
        ".reg .pred P1;\n\t"
        "WAIT_%=:\n\t"
        "mbarrier.try_wait.parity.acquire.cluster.shared::cta.b64 P1, [%0], %1, 0x989680;\n\t"
        "@P1 bra.uni DONE_%=;\n\t"
        "bra.uni WAIT_%=;\n\t"
        "DONE_%=:\n\t"
        "}"
        :: "r"(addr), "r"(parity) : "memory");
}
__device__ __forceinline__ void cluster_barrier() {
    asm volatile("barrier.cluster.arrive.aligned;" ::: "memory");
    asm volatile("barrier.cluster.wait.aligned;" ::: "memory");
}

// ---------------------------------------------------------------------------
// Fast activations: HW tanh unit (sm_75+), sigmoid via tanh identity.
// ---------------------------------------------------------------------------
__device__ __forceinline__ float tanhf_fast(float x) {
    float y;
    asm("tanh.approx.f32 %0, %1;" : "=f"(y) : "f"(x));
    return y;
}

// ---------------------------------------------------------------------------
// Kernel 1: fold projection into layer-0 input weight (tf32-rounded output).
// ---------------------------------------------------------------------------
__global__ void combine_kernel(const float* __restrict__ proj_w,
                               const float* __restrict__ w_ih0) {
    __shared__ float sPW[32][32];
    __shared__ float sWI[32][33];
    int tx = threadIdx.x, ty = threadIdx.y;
    int d0 = blockIdx.x * 32, g0 = blockIdx.y * 32;
    float acc = 0.f;
    for (int p0 = 0; p0 < DP; p0 += 32) {
        sPW[ty][tx] = proj_w[(size_t)(p0 + ty) * DIN + d0 + tx];
        sWI[ty][tx] = w_ih0[(size_t)(g0 + ty) * DP + p0 + tx];
        __syncthreads();
#pragma unroll
        for (int p = 0; p < 32; p++) acc += sPW[p][tx] * sWI[ty][p];
        __syncthreads();
    }
    g_wc[(size_t)(d0 + tx) * G4 + g0 + ty] = to_tf32(acc);
}

__global__ void bias0_kernel(const float* __restrict__ proj_b,
                             const float* __restrict__ w_ih0,
                             const float* __restrict__ b_ih0,
                             const float* __restrict__ b_hh0) {
    int gidx = threadIdx.x;
    float acc = b_ih0[gidx] + b_hh0[gidx];
    const float* wr = w_ih0 + (size_t)gidx * DP;
    for (int p = 0; p < DP; p++) acc += proj_b[p] * wr[p];
    g_bias0[gidx] = acc;
}

// ---------------------------------------------------------------------------
// Kernel 2: layer-0 preactivations via tf32 tensor cores (R11, unchanged).
// ---------------------------------------------------------------------------
#define APAD0 68
#define BPAD0 72
__global__ void __launch_bounds__(256)
xpre0_kernel(const float* __restrict__ in) {
    __shared__ __align__(16) float sIn[128 * 32 + DIN];
    __shared__ __align__(16) float buf[128 * APAD0 + 64 * BPAD0];
    float* sAp = buf;
    float* sWp = buf + 128 * APAD0;
    float* sT  = buf;

    int tid  = threadIdx.x;
    int wid  = tid >> 5, lane = tid & 31;
    int gid  = lane >> 2, tig = lane & 3;
    int wm   = wid >> 1, wn = wid & 1;
    int t0 = blockIdx.x * 128;
    int n0 = blockIdx.y * 64;
    int b  = blockIdx.z;

    const float* inb = in + (size_t)b * SEQ * CIN;
    int base = t0 * CIN;
    for (int i = tid; i < 128 * 32 + DIN; i += 256) {
        int gi = base + i;
        sIn[i] = (gi < SEQ * CIN) ? to_tf32(inb[gi]) : 0.f;
    }

    float acc[2][4][4];
#pragma unroll
    for (int mi = 0; mi < 2; mi++)
#pragma unroll
        for (int ni = 0; ni < 4; ni++)
#pragma unroll
            for (int e = 0; e < 4; e++) acc[mi][ni][e] = 0.f;

    __syncthreads();

    for (int kc = 0; kc < 10; kc++) {
#pragma unroll
        for (int r = 0; r < 8; r++) {
            int j = tid + r * 256;
            int t = j >> 4, k4 = (j & 15) << 2;
            *(float4*)&sAp[t * APAD0 + k4] = *(const float4*)&sIn[t * 32 + kc * 64 + k4];
        }
#pragma unroll
        for (int r = 0; r < 4; r++) {
            int j = tid + r * 256;
            int k = j >> 4, g4 = (j & 15) << 2;
            *(float4*)&sWp[k * BPAD0 + g4] =
                *(const float4*)&g_wc[(size_t)(kc * 64 + k) * G4 + n0 + g4];
        }
        __syncthreads();

#pragma unroll
        for (int ki = 0; ki < 8; ki++) {
            unsigned afr[2][4];
#pragma unroll
            for (int mi = 0; mi < 2; mi++) {
                const float* ar = sAp + (wm * 32 + mi * 16 + gid) * APAD0 + ki * 8 + tig;
                afr[mi][0] = __float_as_uint(ar[0]);
                afr[mi][1] = __float_as_uint(ar[8 * APAD0]);
                afr[mi][2] = __float_as_uint(ar[4]);
                afr[mi][3] = __float_as_uint(ar[8 * APAD0 + 4]);
            }
            unsigned bfr[4][2];
#pragma unroll
            for (int ni = 0; ni < 4; ni++) {
                const float* br = sWp + (ki * 8 + tig) * BPAD0 + wn * 32 + ni * 8 + gid;
                bfr[ni][0] = __float_as_uint(br[0]);
                bfr[ni][1] = __float_as_uint(br[4 * BPAD0]);
            }
#pragma unroll
            for (int mi = 0; mi < 2; mi++)
#pragma unroll
                for (int ni = 0; ni < 4; ni++)
                    mma_tf32(acc[mi][ni], afr[mi], bfr[ni]);
        }
        __syncthreads();
    }

#pragma unroll
    for (int mi = 0; mi < 2; mi++)
#pragma unroll
        for (int ni = 0; ni < 4; ni++) {
            int tl = wm * 32 + mi * 16 + gid;
            int gl = wn * 32 + ni * 8 + tig * 2;
            sT[gl * 132 + tl]           = acc[mi][ni][0];
            sT[(gl + 1) * 132 + tl]     = acc[mi][ni][1];
            sT[gl * 132 + tl + 8]       = acc[mi][ni][2];
            sT[(gl + 1) * 132 + tl + 8] = acc[mi][ni][3];
        }
    __syncthreads();
#pragma unroll
    for (int r = 0; r < 8; r++) {
        int j = tid + r * 256;
        int g = j >> 5, t4 = (j & 31) << 2;
        if (t0 + t4 + 4 <= XT) {
            float4 v = *(float4*)&sT[g * 132 + t4];
            float bv = g_bias0[n0 + g];
            v.x += bv; v.y += bv; v.z += bv; v.w += bv;
            *(float4*)&g_xpre[((size_t)b * G4 + n0 + g) * XT + t0 + t4] = v;
        }
    }
}

// ---------------------------------------------------------------------------
// Kernel 3: input preactivations for layers 1..3 via tf32.
// R15: grid mapping swapped — blockIdx.x = n-block (8), blockIdx.y = t-block
// (32). Consecutively-scheduled CTAs now share the same hseq A-tile, so A is
// served from L2 for 7 of 8 n-blocks instead of re-fetched from DRAM.
// ---------------------------------------------------------------------------
#define APAD1 132
#define BPAD1 72
__global__ void __launch_bounds__(256)
gemm_ih_kernel(const float* __restrict__ w_ih,
               const float* __restrict__ b_ih,
               const float* __restrict__ b_hh) {
    __shared__ __align__(16) float buf[64 * APAD1 + 128 * BPAD1];
    float* sA = buf;
    float* sB = buf + 64 * APAD1;
    float* sT = buf;

    int tid  = threadIdx.x;
    int wid  = tid >> 5, lane = tid & 31;
    int gid  = lane >> 2, tig = lane & 3;
    int wm   = wid & 1, wn = wid >> 1;
    int t0 = blockIdx.y * 64;     // swapped (was blockIdx.x)
    int n0 = blockIdx.x * 64;     // swapped (was blockIdx.y)
    int b  = blockIdx.z;

#pragma unroll
    for (int r = 0; r < 8; r++) {
        int j = tid + r * 256;
        int t = j >> 5, k4 = (j & 31) << 2;
        float4 v = make_float4(0.f, 0.f, 0.f, 0.f);
        if (t0 + t < L_OUT)
            v = *(const float4*)&g_hseq[((size_t)b * L_OUT + t0 + t) * HID + k4];
        v.x = to_tf32(v.x); v.y = to_tf32(v.y); v.z = to_tf32(v.z); v.w = to_tf32(v.w);
        *(float4*)&sA[t * APAD1 + k4] = v;
    }
#pragma unroll
    for (int r = 0; r < 8; r++) {
        int j = tid + r * 256;
        int g = j & 63, kg = j >> 6;
        int k4 = kg << 2;
        float4 v = *(const float4*)&w_ih[(size_t)(n0 + g) * HID + k4];
        sB[(k4 + 0) * BPAD1 + g] = to_tf32(v.x);
        sB[(k4 + 1) * BPAD1 + g] = to_tf32(v.y);
        sB[(k4 + 2) * BPAD1 + g] = to_tf32(v.z);
        sB[(k4 + 3) * BPAD1 + g] = to_tf32(v.w);
    }
    __syncthreads();

    float acc[2][2][4];
#pragma unroll
    for (int mi = 0; mi < 2; mi++)
#pragma unroll
        for (int ni = 0; ni < 2; ni++)
#pragma unroll
            for (int e = 0; e < 4; e++) acc[mi][ni][e] = 0.f;

#pragma unroll
    for (int ki = 0; ki < 16; ki++) {
        unsigned afr[2][4];
#pragma unroll
        for (int mi = 0; mi < 2; mi++) {
            const float* ar = sA + (wm * 32 + mi * 16 + gid) * APAD1 + ki * 8 + tig;
            afr[mi][0] = __float_as_uint(ar[0]);
            afr[mi][1] = __float_as_uint(ar[8 * APAD1]);
            afr[mi][2] = __float_as_uint(ar[4]);
            afr[mi][3] = __float_as_uint(ar[8 * APAD1 + 4]);
        }
        unsigned bfr[2][2];
#pragma unroll
        for (int ni = 0; ni < 2; ni++) {
            const float* br = sB + (ki * 8 + tig) * BPAD1 + wn * 16 + ni * 8 + gid;
            bfr[ni][0] = __float_as_uint(br[0]);
            bfr[ni][1] = __float_as_uint(br[4 * BPAD1]);
        }
#pragma unroll
        for (int mi = 0; mi < 2; mi++)
#pragma unroll
            for (int ni = 0; ni < 2; ni++)
                mma_tf32(acc[mi][ni], afr[mi], bfr[ni]);
    }
    __syncthreads();

#pragma unroll
    for (int mi = 0; mi < 2; mi++)
#pragma unroll
        for (int ni = 0; ni < 2; ni++) {
            int tl = wm * 32 + mi * 16 + gid;
            int gl = wn * 16 + ni * 8 + tig * 2;
            sT[gl * 68 + tl]           = acc[mi][ni][0];
            sT[(gl + 1) * 68 + tl]     = acc[mi][ni][1];
            sT[gl * 68 + tl + 8]       = acc[mi][ni][2];
            sT[(gl + 1) * 68 + tl + 8] = acc[mi][ni][3];
        }
    __syncthreads();
#pragma unroll
    for (int r = 0; r < 4; r++) {
        int j = tid + r * 256;
        int g = j >> 4, t4 = (j & 15) << 2;
        if (t0 + t4 + 4 <= XT) {
            float4 v = *(float4*)&sT[g * 68 + t4];
            float bv = b_ih[n0 + g] + b_hh[n0 + g];
            v.x += bv; v.y += bv; v.z += bv; v.w += bv;
            *(float4*)&g_xpre[((size_t)b * G4 + n0 + g) * XT + t0 + t4] = v;
        }
    }
}

// ---------------------------------------------------------------------------
// Kernel 4: recurrent scan — R12 protocol/structure restored (measured best;
// the R14 early-probe is REVERTED). Kept from R14 only the two strictly-free
// chain cuts: xp folded into accumulator init, and the packed f32x2
// reduction tree (3 add2 + 1 unpack + 1 add).
// ---------------------------------------------------------------------------
__global__ void __cluster_dims__(2, 1, 1) __launch_bounds__(256, 1)
scan_kernel(const float* __restrict__ w_hh) {
    __shared__ __align__(16) float hbuf[2][64];
    __shared__ __align__(16) float land[2][64];
    __shared__ __align__(8) unsigned long long mbars[2];

    int tid  = threadIdx.x;
    int rank = blockIdx.x & 1;
    int b    = blockIdx.x >> 1;
    int gate = tid & 3;
    int ul   = tid >> 2;
    int ug   = rank * 64 + ul;
    int row  = gate * HID + ug;
    int kown  = rank * 64;
    int kpeer = (rank ^ 1) * 64;

    unsigned long long wown[32], wpeer[32];
    {
        const ulonglong2* wr = (const ulonglong2*)(w_hh + (size_t)row * HID + kown);
#pragma unroll
        for (int k = 0; k < 16; k++) {
            ulonglong2 u = wr[k];
            wown[2 * k]     = u.x;
            wown[2 * k + 1] = u.y;
        }
        const ulonglong2* wp = (const ulonglong2*)(w_hh + (size_t)row * HID + kpeer);
#pragma unroll
        for (int k = 0; k < 16; k++) {
            ulonglong2 u = wp[k];
            wpeer[2 * k]     = u.x;
            wpeer[2 * k + 1] = u.y;
        }
    }

    if (tid < 64) {
        hbuf[0][tid] = 0.f; hbuf[1][tid] = 0.f;
        land[0][tid] = 0.f; land[1][tid] = 0.f;
    }
    unsigned bar0 = smem_u32(&mbars[0]);
    unsigned bar1 = smem_u32(&mbars[1]);
    if (tid == 0) { mbar_init(bar0, 1); mbar_init(bar1, 1); }
    __syncthreads();
    cluster_barrier();

    unsigned peer = rank ^ 1;
    unsigned peer_l0 = mapa_rank(smem_u32(&land[0][0]), peer) + (unsigned)ul * 4u;
    unsigned peer_l1 = mapa_rank(smem_u32(&land[1][0]), peer) + (unsigned)ul * 4u;
    unsigned peer_b0 = mapa_rank(bar0, peer);
    unsigned peer_b1 = mapa_rank(bar1, peer);

    float c = 0.f;
    const size_t hrow = (size_t)b * L_OUT;
    const float* xrow_p = g_xpre + ((size_t)b * G4 + row) * XT;

    // activation via tanh unit: act = A*tanh(B*pre) + C
    const float A_ = (gate == 2) ? 1.f : 0.5f;
    const float B_ = (gate == 2) ? 1.f : 0.5f;
    const float C_ = (gate == 2) ? 0.f : 0.5f;
    const bool  tail   = (gate == 0);
    const bool  sender = tail && ((ul & 1) == 0);

    float4 xcur = *(const float4*)(xrow_p);

    for (int t4 = 0; t4 < L_OUT; t4 += 4) {
        float4 xnxt = *(const float4*)(xrow_p + t4 + 4);

#pragma unroll
        for (int s = 0; s < 4; s++) {
            int t = t4 + s;
            float xp = (s == 0) ? xcur.x : (s == 1) ? xcur.y : (s == 2) ? xcur.z : xcur.w;

            if (tid == 0 && t + 1 < L_OUT)
                mbar_expect_tx((t & 1) ? bar1 : bar0, 256);

            // own half (acc0 seeded with xp — folds the final add)
            unsigned long long a0 = pk2(xp, 0.f), a1 = pk2(0.f, 0.f);
            unsigned long long a2 = pk2(0.f, 0.f), a3 = pk2(0.f, 0.f);
            {
                const ulonglong2* h2 = (const ulonglong2*)hbuf[(t + 1) & 1];
#pragma unroll
                for (int k = 0; k < 8; k++) {
                    ulonglong2 u = h2[2 * k];
                    ulonglong2 v = h2[2 * k + 1];
                    fma2(a0, wown[4 * k],     u.x);
                    fma2(a1, wown[4 * k + 1], u.y);
                    fma2(a2, wown[4 * k + 2], v.x);
                    fma2(a3, wown[4 * k + 3], v.y);
                }
            }

            // CTA-uniform blocking wait (R12 placement — probe reverted)
            if (t > 0) {
                int pv = t - 1;
                mbar_wait_cluster((pv & 1) ? bar1 : bar0, (unsigned)((pv >> 1) & 1));
            }

            // peer half from landing buffer
            {
                const ulonglong2* h2 = (const ulonglong2*)land[(t + 1) & 1];
#pragma unroll
                for (int k = 0; k < 8; k++) {
                    ulonglong2 u = h2[2 * k];
                    ulonglong2 v = h2[2 * k + 1];
                    fma2(a0, wpeer[4 * k],     u.x);
                    fma2(a1, wpeer[4 * k + 1], u.y);
                    fma2(a2, wpeer[4 * k + 2], v.x);
                    fma2(a3, wpeer[4 * k + 3], v.y);
                }
            }

            // packed reduction tree
            float2 q = unpk2(add2(add2(a0, a1), add2(a2, a3)));
            float pre = q.x + q.y;
            float act = fmaf(A_, tanhf_fast(B_ * pre), C_);

            float fv = __shfl_down_sync(0xffffffffu, act, 1);
            float gv = __shfl_down_sync(0xffffffffu, act, 2);
            float ov = __shfl_down_sync(0xffffffffu, act, 3);

            float h = 0.f;
            if (tail) {
                c = fmaf(fv, c, act * gv);        // act == i
                h = ov * tanhf_fast(c);
            }
            float hp = __shfl_down_sync(0xffffffffu, h, 4);
            if (tail) {
                if (sender && t + 1 < L_OUT)
                    st_async_f32x2((t & 1) ? peer_l1 : peer_l0, h, hp,
                                   (t & 1) ? peer_b1 : peer_b0);
                hbuf[t & 1][ul] = h;
                g_hseq[(hrow + t) * HID + ug] = h;
            }
            __syncthreads();
        }
        xcur = xnxt;
    }
    cluster_barrier();
}

// ---------------------------------------------------------------------------
// Kernel 5: readout.
// ---------------------------------------------------------------------------
__global__ void out_kernel(const float* __restrict__ out_w,
                           const float* __restrict__ out_b,
                           float* __restrict__ out) {
    __shared__ float h[HID];
    int b = blockIdx.x;
    if (threadIdx.x < HID)
        h[threadIdx.x] = g_hseq[((size_t)b * L_OUT + (L_OUT - 1)) * HID + threadIdx.x];
    __syncthreads();
    if (threadIdx.x < LBL) {
        float acc = out_b[threadIdx.x];
        const float* wr = out_w + (size_t)threadIdx.x * HID;
#pragma unroll 8
        for (int k = 0; k < HID; k++) acc += wr[k] * h[k];
        out[(size_t)b * LBL + threadIdx.x] = acc;
    }
}

// ---------------------------------------------------------------------------
// Launch
// ---------------------------------------------------------------------------
extern "C" void kernel_launch(void* const* d_in, const int* in_sizes, int n_in,
                              void* d_out, int out_size) {
    const float* inputs    = (const float*)d_in[0];
    const float* proj_w    = (const float*)d_in[4];
    const float* proj_b    = (const float*)d_in[5];
    const float* w_ih0     = (const float*)d_in[6];
    const float* w_hh0     = (const float*)d_in[7];
    const float* b_ih0     = (const float*)d_in[8];
    const float* b_hh0     = (const float*)d_in[9];
    const float* w_ih_rest = (const float*)d_in[10];
    const float* w_hh_rest = (const float*)d_in[11];
    const float* b_ih_rest = (const float*)d_in[12];
    const float* b_hh_rest = (const float*)d_in[13];
    const float* out_w     = (const float*)d_in[14];
    const float* out_b     = (const float*)d_in[15];
    float* out = (float*)d_out;

    combine_kernel<<<dim3(DIN / 32, G4 / 32), dim3(32, 32)>>>(proj_w, w_ih0);
    bias0_kernel<<<1, G4>>>(proj_b, w_ih0, b_ih0, b_hh0);

    xpre0_kernel<<<dim3((L_OUT + 127) / 128, G4 / 64, BATCH), 256>>>(inputs);

    scan_kernel<<<BATCH * 2, 256>>>(w_hh0);

    for (int l = 0; l < 3; l++) {
        // grid mapping swapped for L2 reuse of the hseq A-tile: x = n-block
        gemm_ih_kernel<<<dim3(G4 / 64, (L_OUT + 63) / 64, BATCH), 256>>>(
            w_ih_rest + (size_t)l * G4 * HID,
            b_ih_rest + (size_t)l * G4,
            b_hh_rest + (size_t)l * G4);
        scan_kernel<<<BATCH * 2, 256>>>(w_hh_rest + (size_t)l * G4 * HID);
    }

    out_kernel<<<BATCH, 128>>>(out_w, out_b, out);
}

// round 16
// speedup vs baseline: 1.0613x; 1.0178x over previous
#include <cuda_runtime.h>
#include <cuda_bf16.h>
#include <cstdint>

// ---------------------------------------------------------------------------
// Problem constants
// ---------------------------------------------------------------------------
#define BATCH   64
#define SEQ     2048
#define CIN     32
#define WIN     20
#define DIN     (WIN * CIN)      // 640
#define DP      (DIN / 2)        // 320
#define HID     128
#define G4      (4 * HID)        // 512
#define L_OUT   (SEQ - WIN)      // 2028
#define XT      2032             // padded time stride for g_xpre
#define LBL     48

// ---------------------------------------------------------------------------
// Scratch (static __device__ arrays; no cudaMalloc allowed)
// ---------------------------------------------------------------------------
__device__ float g_wc[DIN * G4];                       // combined proj->ih0 weight [k][g], tf32-rounded
__device__ float g_bias0[G4];
__device__ float g_xpre[(size_t)BATCH * G4 * XT];      // preactivations, [b][g][t] (t-major)
__device__ float g_hseq[(size_t)BATCH * L_OUT * HID];  // per-step hidden outputs [b][t][h]

// ---------------------------------------------------------------------------
// Packed fp32x2 helpers (scan only)
// ---------------------------------------------------------------------------
__device__ __forceinline__ unsigned long long pk2(float x, float y) {
    unsigned long long r;
    asm("mov.b64 %0, {%1, %2};" : "=l"(r) : "f"(x), "f"(y));
    return r;
}
__device__ __forceinline__ float2 unpk2(unsigned long long v) {
    float2 r;
    asm("mov.b64 {%0, %1}, %2;" : "=f"(r.x), "=f"(r.y) : "l"(v));
    return r;
}
__device__ __forceinline__ void fma2(unsigned long long& d, unsigned long long a,
                                     unsigned long long b) {
    asm("fma.rn.f32x2 %0, %1, %2, %3;" : "=l"(d) : "l"(a), "l"(b), "l"(d));
}
__device__ __forceinline__ unsigned long long add2(unsigned long long a,
                                                   unsigned long long b) {
    unsigned long long r;
    asm("add.rn.f32x2 %0, %1, %2;" : "=l"(r) : "l"(a), "l"(b));
    return r;
}

// ---------------------------------------------------------------------------
// tf32 helpers
// ---------------------------------------------------------------------------
__device__ __forceinline__ float to_tf32(float x) {
    unsigned u;
    asm("cvt.rna.tf32.f32 %0, %1;" : "=r"(u) : "f"(x));
    return __uint_as_float(u);
}
// D(16x8,f32) += A(16x8 tf32, row) * B(8x8 tf32, col)
__device__ __forceinline__ void mma_tf32(float* d, const unsigned* a, const unsigned* b) {
    asm volatile(
        "mma.sync.aligned.m16n8k8.row.col.f32.tf32.tf32.f32 "
        "{%0,%1,%2,%3}, {%4,%5,%6,%7}, {%8,%9}, {%0,%1,%2,%3};"
        : "+f"(d[0]), "+f"(d[1]), "+f"(d[2]), "+f"(d[3])
        : "r"(a[0]), "r"(a[1]), "r"(a[2]), "r"(a[3]), "r"(b[0]), "r"(b[1]));
}

// ---------------------------------------------------------------------------
// Cluster / mbarrier helpers
// ---------------------------------------------------------------------------
__device__ __forceinline__ unsigned smem_u32(const void* p) {
    return (unsigned)__cvta_generic_to_shared(p);
}
__device__ __forceinline__ unsigned mapa_rank(unsigned addr, unsigned rank) {
    unsigned r;
    asm("mapa.shared::cluster.u32 %0, %1, %2;" : "=r"(r) : "r"(addr), "r"(rank));
    return r;
}
__device__ __forceinline__ void mbar_init(unsigned addr, unsigned cnt) {
    asm volatile("mbarrier.init.shared.b64 [%0], %1;" :: "r"(addr), "r"(cnt) : "memory");
}
__device__ __forceinline__ void mbar_expect_tx(unsigned addr, unsigned bytes) {
    asm volatile("mbarrier.arrive.expect_tx.shared.b64 _, [%0], %1;"
                 :: "r"(addr), "r"(bytes) : "memory");
}
// Packed remote SMEM store (8 bytes) with mbarrier tx-completion.
__device__ __forceinline__ void st_async_f32x2(unsigned raddr, float x, float y,
                                               unsigned rmbar) {
    unsigned long long v = pk2(x, y);   // little-endian: x at raddr, y at raddr+4
    asm volatile(
        "st.async.shared::cluster.mbarrier::complete_tx::bytes.b64 [%0], %1, [%2];"
        :: "r"(raddr), "l"(v), "r"(rmbar) : "memory");
}
__device__ __forceinline__ void mbar_wait_cluster(unsigned addr, unsigned parity) {
    asm volatile(
        "{\n\t"
        ".reg .pred P1;\n\t"
        "WAIT_%=:\n\t"
        "mbarrier.try_wait.parity.acquire.cluster.shared::cta.b64 P1, [%0], %1, 0x989680;\n\t"
        "@P1 bra.uni DONE_%=;\n\t"
        "bra.uni WAIT_%=;\n\t"
        "DONE_%=:\n\t"
        "}"
        :: "r"(addr), "r"(parity) : "memory");
}
__device__ __forceinline__ void cluster_barrier() {
    asm volatile("barrier.cluster.arrive.aligned;" ::: "memory");
    asm volatile("barrier.cluster.wait.aligned;" ::: "memory");
}

// ---------------------------------------------------------------------------
// Fast activations: HW tanh unit (sm_75+), sigmoid via tanh identity.
// ---------------------------------------------------------------------------
__device__ __forceinline__ float tanhf_fast(float x) {
    float y;
    asm("tanh.approx.f32 %0, %1;" : "=f"(y) : "f"(x));
    return y;
}

// ---------------------------------------------------------------------------
// Kernel 1: fold projection into layer-0 input weight (tf32-rounded output).
// ---------------------------------------------------------------------------
__global__ void combine_kernel(const float* __restrict__ proj_w,
                               const float* __restrict__ w_ih0) {
    __shared__ float sPW[32][32];
    __shared__ float sWI[32][33];
    int tx = threadIdx.x, ty = threadIdx.y;
    int d0 = blockIdx.x * 32, g0 = blockIdx.y * 32;
    float acc = 0.f;
    for (int p0 = 0; p0 < DP; p0 += 32) {
        sPW[ty][tx] = proj_w[(size_t)(p0 + ty) * DIN + d0 + tx];
        sWI[ty][tx] = w_ih0[(size_t)(g0 + ty) * DP + p0 + tx];
        __syncthreads();
#pragma unroll
        for (int p = 0; p < 32; p++) acc += sPW[p][tx] * sWI[ty][p];
        __syncthreads();
    }
    g_wc[(size_t)(d0 + tx) * G4 + g0 + ty] = to_tf32(acc);
}

// R16: parallelized — one block per gate row, 64-thread reduction
// (was <<<1,512>>> with a 320-iteration serial loop on a single SM).
__global__ void bias0_kernel(const float* __restrict__ proj_b,
                             const float* __restrict__ w_ih0,
                             const float* __restrict__ b_ih0,
                             const float* __restrict__ b_hh0) {
    __shared__ float red[64];
    int g = blockIdx.x;
    const float* wr = w_ih0 + (size_t)g * DP;
    float acc = 0.f;
    for (int p = threadIdx.x; p < DP; p += 64) acc += proj_b[p] * wr[p];
    red[threadIdx.x] = acc;
    __syncthreads();
    if (threadIdx.x < 32) {
        float s = red[threadIdx.x] + red[threadIdx.x + 32];
#pragma unroll
        for (int o = 16; o > 0; o >>= 1) s += __shfl_down_sync(0xffffffffu, s, o);
        if (threadIdx.x == 0) g_bias0[g] = b_ih0[g] + b_hh0[g] + s;
    }
}

// ---------------------------------------------------------------------------
// Kernel 2: layer-0 preactivations via tf32 tensor cores.
// R16: A chunk staged DIRECTLY from gmem (the window is a contiguous slice)
// with on-the-fly tf32 rounding — removes the sIn double-staging hop, one
// __syncthreads, and 19 KB SMEM (occupancy 3 -> 4 CTAs/SM).
// ---------------------------------------------------------------------------
#define APAD0 68
#define BPAD0 72
__global__ void __launch_bounds__(256)
xpre0_kernel(const float* __restrict__ in) {
    __shared__ __align__(16) float buf[128 * APAD0 + 64 * BPAD0];
    float* sAp = buf;                     // [128][APAD0]
    float* sWp = buf + 128 * APAD0;       // [64][BPAD0]
    float* sT  = buf;                     // epilogue alias [64][132]

    int tid  = threadIdx.x;
    int wid  = tid >> 5, lane = tid & 31;
    int gid  = lane >> 2, tig = lane & 3;
    int wm   = wid >> 1, wn = wid & 1;
    int t0 = blockIdx.x * 128;
    int n0 = blockIdx.y * 64;
    int b  = blockIdx.z;

    const float* inb = in + (size_t)b * SEQ * CIN;
    int base = t0 * CIN;

    float acc[2][4][4];
#pragma unroll
    for (int mi = 0; mi < 2; mi++)
#pragma unroll
        for (int ni = 0; ni < 4; ni++)
#pragma unroll
            for (int e = 0; e < 4; e++) acc[mi][ni][e] = 0.f;

    for (int kc = 0; kc < 10; kc++) {
        // stage A chunk directly from gmem: sAp[t][kk] = tf32(in[base + t*32 + kc*64 + kk])
#pragma unroll
        for (int r = 0; r < 8; r++) {
            int j = tid + r * 256;          // 2048 float4
            int t = j >> 4, k4 = (j & 15) << 2;
            int gi = base + t * CIN + kc * 64 + k4;
            float4 v = make_float4(0.f, 0.f, 0.f, 0.f);
            if (gi + 4 <= SEQ * CIN) v = *(const float4*)&inb[gi];
            v.x = to_tf32(v.x); v.y = to_tf32(v.y);
            v.z = to_tf32(v.z); v.w = to_tf32(v.w);
            *(float4*)&sAp[t * APAD0 + k4] = v;
        }
        // stage B chunk: sWp[k][g] from g_wc (pre-rounded)
#pragma unroll
        for (int r = 0; r < 4; r++) {
            int j = tid + r * 256;          // 1024 float4
            int k = j >> 4, g4 = (j & 15) << 2;
            *(float4*)&sWp[k * BPAD0 + g4] =
                *(const float4*)&g_wc[(size_t)(kc * 64 + k) * G4 + n0 + g4];
        }
        __syncthreads();

#pragma unroll
        for (int ki = 0; ki < 8; ki++) {
            unsigned afr[2][4];
#pragma unroll
            for (int mi = 0; mi < 2; mi++) {
                const float* ar = sAp + (wm * 32 + mi * 16 + gid) * APAD0 + ki * 8 + tig;
                afr[mi][0] = __float_as_uint(ar[0]);
                afr[mi][1] = __float_as_uint(ar[8 * APAD0]);
                afr[mi][2] = __float_as_uint(ar[4]);
                afr[mi][3] = __float_as_uint(ar[8 * APAD0 + 4]);
            }
            unsigned bfr[4][2];
#pragma unroll
            for (int ni = 0; ni < 4; ni++) {
                const float* br = sWp + (ki * 8 + tig) * BPAD0 + wn * 32 + ni * 8 + gid;
                bfr[ni][0] = __float_as_uint(br[0]);
                bfr[ni][1] = __float_as_uint(br[4 * BPAD0]);
            }
#pragma unroll
            for (int mi = 0; mi < 2; mi++)
#pragma unroll
                for (int ni = 0; ni < 4; ni++)
                    mma_tf32(acc[mi][ni], afr[mi], bfr[ni]);
        }
        __syncthreads();
    }

    // epilogue: transpose to sT[g][t] (pad 132), then coalesced stores + bias
#pragma unroll
    for (int mi = 0; mi < 2; mi++)
#pragma unroll
        for (int ni = 0; ni < 4; ni++) {
            int tl = wm * 32 + mi * 16 + gid;
            int gl = wn * 32 + ni * 8 + tig * 2;
            sT[gl * 132 + tl]           = acc[mi][ni][0];
            sT[(gl + 1) * 132 + tl]     = acc[mi][ni][1];
            sT[gl * 132 + tl + 8]       = acc[mi][ni][2];
            sT[(gl + 1) * 132 + tl + 8] = acc[mi][ni][3];
        }
    __syncthreads();
#pragma unroll
    for (int r = 0; r < 8; r++) {
        int j = tid + r * 256;              // 2048 float4
        int g = j >> 5, t4 = (j & 31) << 2;
        if (t0 + t4 + 4 <= XT) {
            float4 v = *(float4*)&sT[g * 132 + t4];
            float bv = g_bias0[n0 + g];
            v.x += bv; v.y += bv; v.z += bv; v.w += bv;
            *(float4*)&g_xpre[((size_t)b * G4 + n0 + g) * XT + t0 + t4] = v;
        }
    }
}

// ---------------------------------------------------------------------------
// Kernel 3: input preactivations for layers 1..3 via tf32 (R15, unchanged —
// grid mapping keeps n-blocks adjacent for L2 reuse of the hseq A-tile).
// ---------------------------------------------------------------------------
#define APAD1 132
#define BPAD1 72
__global__ void __launch_bounds__(256)
gemm_ih_kernel(const float* __restrict__ w_ih,
               const float* __restrict__ b_ih,
               const float* __restrict__ b_hh) {
    __shared__ __align__(16) float buf[64 * APAD1 + 128 * BPAD1];
    float* sA = buf;
    float* sB = buf + 64 * APAD1;
    float* sT = buf;

    int tid  = threadIdx.x;
    int wid  = tid >> 5, lane = tid & 31;
    int gid  = lane >> 2, tig = lane & 3;
    int wm   = wid & 1, wn = wid >> 1;
    int t0 = blockIdx.y * 64;
    int n0 = blockIdx.x * 64;
    int b  = blockIdx.z;

#pragma unroll
    for (int r = 0; r < 8; r++) {
        int j = tid + r * 256;
        int t = j >> 5, k4 = (j & 31) << 2;
        float4 v = make_float4(0.f, 0.f, 0.f, 0.f);
        if (t0 + t < L_OUT)
            v = *(const float4*)&g_hseq[((size_t)b * L_OUT + t0 + t) * HID + k4];
        v.x = to_tf32(v.x); v.y = to_tf32(v.y); v.z = to_tf32(v.z); v.w = to_tf32(v.w);
        *(float4*)&sA[t * APAD1 + k4] = v;
    }
#pragma unroll
    for (int r = 0; r < 8; r++) {
        int j = tid + r * 256;
        int g = j & 63, kg = j >> 6;
        int k4 = kg << 2;
        float4 v = *(const float4*)&w_ih[(size_t)(n0 + g) * HID + k4];
        sB[(k4 + 0) * BPAD1 + g] = to_tf32(v.x);
        sB[(k4 + 1) * BPAD1 + g] = to_tf32(v.y);
        sB[(k4 + 2) * BPAD1 + g] = to_tf32(v.z);
        sB[(k4 + 3) * BPAD1 + g] = to_tf32(v.w);
    }
    __syncthreads();

    float acc[2][2][4];
#pragma unroll
    for (int mi = 0; mi < 2; mi++)
#pragma unroll
        for (int ni = 0; ni < 2; ni++)
#pragma unroll
            for (int e = 0; e < 4; e++) acc[mi][ni][e] = 0.f;

#pragma unroll
    for (int ki = 0; ki < 16; ki++) {
        unsigned afr[2][4];
#pragma unroll
        for (int mi = 0; mi < 2; mi++) {
            const float* ar = sA + (wm * 32 + mi * 16 + gid) * APAD1 + ki * 8 + tig;
            afr[mi][0] = __float_as_uint(ar[0]);
            afr[mi][1] = __float_as_uint(ar[8 * APAD1]);
            afr[mi][2] = __float_as_uint(ar[4]);
            afr[mi][3] = __float_as_uint(ar[8 * APAD1 + 4]);
        }
        unsigned bfr[2][2];
#pragma unroll
        for (int ni = 0; ni < 2; ni++) {
            const float* br = sB + (ki * 8 + tig) * BPAD1 + wn * 16 + ni * 8 + gid;
            bfr[ni][0] = __float_as_uint(br[0]);
            bfr[ni][1] = __float_as_uint(br[4 * BPAD1]);
        }
#pragma unroll
        for (int mi = 0; mi < 2; mi++)
#pragma unroll
            for (int ni = 0; ni < 2; ni++)
                mma_tf32(acc[mi][ni], afr[mi], bfr[ni]);
    }
    __syncthreads();

#pragma unroll
    for (int mi = 0; mi < 2; mi++)
#pragma unroll
        for (int ni = 0; ni < 2; ni++) {
            int tl = wm * 32 + mi * 16 + gid;
            int gl = wn * 16 + ni * 8 + tig * 2;
            sT[gl * 68 + tl]           = acc[mi][ni][0];
            sT[(gl + 1) * 68 + tl]     = acc[mi][ni][1];
            sT[gl * 68 + tl + 8]       = acc[mi][ni][2];
            sT[(gl + 1) * 68 + tl + 8] = acc[mi][ni][3];
        }
    __syncthreads();
#pragma unroll
    for (int r = 0; r < 4; r++) {
        int j = tid + r * 256;
        int g = j >> 4, t4 = (j & 15) << 2;
        if (t0 + t4 + 4 <= XT) {
            float4 v = *(float4*)&sT[g * 68 + t4];
            float bv = b_ih[n0 + g] + b_hh[n0 + g];
            v.x += bv; v.y += bv; v.z += bv; v.w += bv;
            *(float4*)&g_xpre[((size_t)b * G4 + n0 + g) * XT + t0 + t4] = v;
        }
    }
}

// ---------------------------------------------------------------------------
// Kernel 4: recurrent scan — bitwise R15 (measured best).
// ---------------------------------------------------------------------------
__global__ void __cluster_dims__(2, 1, 1) __launch_bounds__(256, 1)
scan_kernel(const float* __restrict__ w_hh) {
    __shared__ __align__(16) float hbuf[2][64];
    __shared__ __align__(16) float land[2][64];
    __shared__ __align__(8) unsigned long long mbars[2];

    int tid  = threadIdx.x;
    int rank = blockIdx.x & 1;
    int b    = blockIdx.x >> 1;
    int gate = tid & 3;
    int ul   = tid >> 2;
    int ug   = rank * 64 + ul;
    int row  = gate * HID + ug;
    int kown  = rank * 64;
    int kpeer = (rank ^ 1) * 64;

    unsigned long long wown[32], wpeer[32];
    {
        const ulonglong2* wr = (const ulonglong2*)(w_hh + (size_t)row * HID + kown);
#pragma unroll
        for (int k = 0; k < 16; k++) {
            ulonglong2 u = wr[k];
            wown[2 * k]     = u.x;
            wown[2 * k + 1] = u.y;
        }
        const ulonglong2* wp = (const ulonglong2*)(w_hh + (size_t)row * HID + kpeer);
#pragma unroll
        for (int k = 0; k < 16; k++) {
            ulonglong2 u = wp[k];
            wpeer[2 * k]     = u.x;
            wpeer[2 * k + 1] = u.y;
        }
    }

    if (tid < 64) {
        hbuf[0][tid] = 0.f; hbuf[1][tid] = 0.f;
        land[0][tid] = 0.f; land[1][tid] = 0.f;
    }
    unsigned bar0 = smem_u32(&mbars[0]);
    unsigned bar1 = smem_u32(&mbars[1]);
    if (tid == 0) { mbar_init(bar0, 1); mbar_init(bar1, 1); }
    __syncthreads();
    cluster_barrier();

    unsigned peer = rank ^ 1;
    unsigned peer_l0 = mapa_rank(smem_u32(&land[0][0]), peer) + (unsigned)ul * 4u;
    unsigned peer_l1 = mapa_rank(smem_u32(&land[1][0]), peer) + (unsigned)ul * 4u;
    unsigned peer_b0 = mapa_rank(bar0, peer);
    unsigned peer_b1 = mapa_rank(bar1, peer);

    float c = 0.f;
    const size_t hrow = (size_t)b * L_OUT;
    const float* xrow_p = g_xpre + ((size_t)b * G4 + row) * XT;

    const float A_ = (gate == 2) ? 1.f : 0.5f;
    const float B_ = (gate == 2) ? 1.f : 0.5f;
    const float C_ = (gate == 2) ? 0.f : 0.5f;
    const bool  tail   = (gate == 0);
    const bool  sender = tail && ((ul & 1) == 0);

    float4 xcur = *(const float4*)(xrow_p);

    for (int t4 = 0; t4 < L_OUT; t4 += 4) {
        float4 xnxt = *(const float4*)(xrow_p + t4 + 4);

#pragma unroll
        for (int s = 0; s < 4; s++) {
            int t = t4 + s;
            float xp = (s == 0) ? xcur.x : (s == 1) ? xcur.y : (s == 2) ? xcur.z : xcur.w;

            if (tid == 0 && t + 1 < L_OUT)
                mbar_expect_tx((t & 1) ? bar1 : bar0, 256);

            unsigned long long a0 = pk2(xp, 0.f), a1 = pk2(0.f, 0.f);
            unsigned long long a2 = pk2(0.f, 0.f), a3 = pk2(0.f, 0.f);
            {
                const ulonglong2* h2 = (const ulonglong2*)hbuf[(t + 1) & 1];
#pragma unroll
                for (int k = 0; k < 8; k++) {
                    ulonglong2 u = h2[2 * k];
                    ulonglong2 v = h2[2 * k + 1];
                    fma2(a0, wown[4 * k],     u.x);
                    fma2(a1, wown[4 * k + 1], u.y);
                    fma2(a2, wown[4 * k + 2], v.x);
                    fma2(a3, wown[4 * k + 3], v.y);
                }
            }

            if (t > 0) {
                int pv = t - 1;
                mbar_wait_cluster((pv & 1) ? bar1 : bar0, (unsigned)((pv >> 1) & 1));
            }

            {
                const ulonglong2* h2 = (const ulonglong2*)land[(t + 1) & 1];
#pragma unroll
                for (int k = 0; k < 8; k++) {
                    ulonglong2 u = h2[2 * k];
                    ulonglong2 v = h2[2 * k + 1];
                    fma2(a0, wpeer[4 * k],     u.x);
                    fma2(a1, wpeer[4 * k + 1], u.y);
                    fma2(a2, wpeer[4 * k + 2], v.x);
                    fma2(a3, wpeer[4 * k + 3], v.y);
                }
            }

            float2 q = unpk2(add2(add2(a0, a1), add2(a2, a3)));
            float pre = q.x + q.y;
            float act = fmaf(A_, tanhf_fast(B_ * pre), C_);

            float fv = __shfl_down_sync(0xffffffffu, act, 1);
            float gv = __shfl_down_sync(0xffffffffu, act, 2);
            float ov = __shfl_down_sync(0xffffffffu, act, 3);

            float h = 0.f;
            if (tail) {
                c = fmaf(fv, c, act * gv);
                h = ov * tanhf_fast(c);
            }
            float hp = __shfl_down_sync(0xffffffffu, h, 4);
            if (tail) {
                if (sender && t + 1 < L_OUT)
                    st_async_f32x2((t & 1) ? peer_l1 : peer_l0, h, hp,
                                   (t & 1) ? peer_b1 : peer_b0);
                hbuf[t & 1][ul] = h;
                g_hseq[(hrow + t) * HID + ug] = h;
            }
            __syncthreads();
        }
        xcur = xnxt;
    }
    cluster_barrier();
}

// ---------------------------------------------------------------------------
// Kernel 5: readout.
// ---------------------------------------------------------------------------
__global__ void out_kernel(const float* __restrict__ out_w,
                           const float* __restrict__ out_b,
                           float* __restrict__ out) {
    __shared__ float h[HID];
    int b = blockIdx.x;
    if (threadIdx.x < HID)
        h[threadIdx.x] = g_hseq[((size_t)b * L_OUT + (L_OUT - 1)) * HID + threadIdx.x];
    __syncthreads();
    if (threadIdx.x < LBL) {
        float acc = out_b[threadIdx.x];
        const float* wr = out_w + (size_t)threadIdx.x * HID;
#pragma unroll 8
        for (int k = 0; k < HID; k++) acc += wr[k] * h[k];
        out[(size_t)b * LBL + threadIdx.x] = acc;
    }
}

// ---------------------------------------------------------------------------
// Launch
// ---------------------------------------------------------------------------
extern "C" void kernel_launch(void* const* d_in, const int* in_sizes, int n_in,
                              void* d_out, int out_size) {
    const float* inputs    = (const float*)d_in[0];
    const float* proj_w    = (const float*)d_in[4];
    const float* proj_b    = (const float*)d_in[5];
    const float* w_ih0     = (const float*)d_in[6];
    const float* w_hh0     = (const float*)d_in[7];
    const float* b_ih0     = (const float*)d_in[8];
    const float* b_hh0     = (const float*)d_in[9];
    const float* w_ih_rest = (const float*)d_in[10];
    const float* w_hh_rest = (const float*)d_in[11];
    const float* b_ih_rest = (const float*)d_in[12];
    const float* b_hh_rest = (const float*)d_in[13];
    const float* out_w     = (const float*)d_in[14];
    const float* out_b     = (const float*)d_in[15];
    float* out = (float*)d_out;

    combine_kernel<<<dim3(DIN / 32, G4 / 32), dim3(32, 32)>>>(proj_w, w_ih0);
    bias0_kernel<<<G4, 64>>>(proj_b, w_ih0, b_ih0, b_hh0);

    xpre0_kernel<<<dim3((L_OUT + 127) / 128, G4 / 64, BATCH), 256>>>(inputs);

    scan_kernel<<<BATCH * 2, 256>>>(w_hh0);

    for (int l = 0; l < 3; l++) {
        gemm_ih_kernel<<<dim3(G4 / 64, (L_OUT + 63) / 64, BATCH), 256>>>(
            w_ih_rest + (size_t)l * G4 * HID,
            b_ih_rest + (size_t)l * G4,
            b_hh_rest + (size_t)l * G4);
        scan_kernel<<<BATCH * 2, 256>>>(w_hh_rest + (size_t)l * G4 * HID);
    }

    out_kernel<<<BATCH, 128>>>(out_w, out_b, out);
}

// round 17
// speedup vs baseline: 1.0926x; 1.0295x over previous
#include <cuda_runtime.h>
#include <cuda_bf16.h>
#include <cstdint>

// ---------------------------------------------------------------------------
// Problem constants
// ---------------------------------------------------------------------------
#define BATCH   64
#define SEQ     2048
#define CIN     32
#define WIN     20
#define DIN     (WIN * CIN)      // 640
#define DP      (DIN / 2)        // 320
#define HID     128
#define G4      (4 * HID)        // 512
#define L_OUT   (SEQ - WIN)      // 2028
#define XT      2032             // padded time stride for g_xpre
#define LBL     48

// ---------------------------------------------------------------------------
// Scratch (static __device__ arrays; no cudaMalloc allowed)
// ---------------------------------------------------------------------------
__device__ float g_wc[DIN * G4];                       // combined proj->ih0 weight [k][g], tf32-rounded
__device__ float g_bias0[G4];
__device__ float g_xpre[(size_t)BATCH * G4 * XT];      // preactivations, [b][g][t] (t-major)
__device__ float g_hseq[(size_t)BATCH * L_OUT * HID];  // per-step hidden outputs [b][t][h]

// ---------------------------------------------------------------------------
// Packed fp32x2 helpers (scan only)
// ---------------------------------------------------------------------------
__device__ __forceinline__ unsigned long long pk2(float x, float y) {
    unsigned long long r;
    asm("mov.b64 %0, {%1, %2};" : "=l"(r) : "f"(x), "f"(y));
    return r;
}
__device__ __forceinline__ float2 unpk2(unsigned long long v) {
    float2 r;
    asm("mov.b64 {%0, %1}, %2;" : "=f"(r.x), "=f"(r.y) : "l"(v));
    return r;
}
__device__ __forceinline__ void fma2(unsigned long long& d, unsigned long long a,
                                     unsigned long long b) {
    asm("fma.rn.f32x2 %0, %1, %2, %3;" : "=l"(d) : "l"(a), "l"(b), "l"(d));
}
__device__ __forceinline__ unsigned long long add2(unsigned long long a,
                                                   unsigned long long b) {
    unsigned long long r;
    asm("add.rn.f32x2 %0, %1, %2;" : "=l"(r) : "l"(a), "l"(b));
    return r;
}

// ---------------------------------------------------------------------------
// tf32 helpers
// ---------------------------------------------------------------------------
__device__ __forceinline__ float to_tf32(float x) {
    unsigned u;
    asm("cvt.rna.tf32.f32 %0, %1;" : "=r"(u) : "f"(x));
    return __uint_as_float(u);
}
// D(16x8,f32) += A(16x8 tf32, row) * B(8x8 tf32, col)
__device__ __forceinline__ void mma_tf32(float* d, const unsigned* a, const unsigned* b) {
    asm volatile(
        "mma.sync.aligned.m16n8k8.row.col.f32.tf32.tf32.f32 "
        "{%0,%1,%2,%3}, {%4,%5,%6,%7}, {%8,%9}, {%0,%1,%2,%3};"
        : "+f"(d[0]), "+f"(d[1]), "+f"(d[2]), "+f"(d[3])
        : "r"(a[0]), "r"(a[1]), "r"(a[2]), "r"(a[3]), "r"(b[0]), "r"(b[1]));
}

// ---------------------------------------------------------------------------
// Cluster / mbarrier helpers
// ---------------------------------------------------------------------------
__device__ __forceinline__ unsigned smem_u32(const void* p) {
    return (unsigned)__cvta_generic_to_shared(p);
}
__device__ __forceinline__ unsigned mapa_rank(unsigned addr, unsigned rank) {
    unsigned r;
    asm("mapa.shared::cluster.u32 %0, %1, %2;" : "=r"(r) : "r"(addr), "r"(rank));
    return r;
}
__device__ __forceinline__ void mbar_init(unsigned addr, unsigned cnt) {
    asm volatile("mbarrier.init.shared.b64 [%0], %1;" :: "r"(addr), "r"(cnt) : "memory");
}
__device__ __forceinline__ void mbar_expect_tx(unsigned addr, unsigned bytes) {
    asm volatile("mbarrier.arrive.expect_tx.shared.b64 _, [%0], %1;"
                 :: "r"(addr), "r"(bytes) : "memory");
}
// Packed remote SMEM store (8 bytes) with mbarrier tx-completion.
__device__ __forceinline__ void st_async_f32x2(unsigned raddr, float x, float y,
                                               unsigned rmbar) {
    unsigned long long v = pk2(x, y);   // little-endian: x at raddr, y at raddr+4
    asm volatile(
        "st.async.shared::cluster.mbarrier::complete_tx::bytes.b64 [%0], %1, [%2];"
        :: "r"(raddr), "l"(v), "r"(rmbar) : "memory");
}
__device__ __forceinline__ void mbar_wait_cluster(unsigned addr, unsigned parity) {
    asm volatile(
        "{\n\t"
        ".reg .pred P1;\n\t"
        "WAIT_%=:\n\t"
        "mbarrier.try_wait.parity.acquire.cluster.shared::cta.b64 P1, [%0], %1, 0x989680;\n\t"
        "@P1 bra.uni DONE_%=;\n\t"
        "bra.uni WAIT_%=;\n\t"
        "DONE_%=:\n\t"
        "}"
        :: "r"(addr), "r"(parity) : "memory");
}
__device__ __forceinline__ void cluster_barrier() {
    asm volatile("barrier.cluster.arrive.aligned;" ::: "memory");
    asm volatile("barrier.cluster.wait.aligned;" ::: "memory");
}

// ---------------------------------------------------------------------------
// Fast activations: HW tanh unit (sm_75+), sigmoid via tanh identity.
// ---------------------------------------------------------------------------
__device__ __forceinline__ float tanhf_fast(float x) {
    float y;
    asm("tanh.approx.f32 %0, %1;" : "=f"(y) : "f"(x));
    return y;
}

// ---------------------------------------------------------------------------
// Kernel 1: fold projection into layer-0 input weight (tf32-rounded output).
// ---------------------------------------------------------------------------
__global__ void combine_kernel(const float* __restrict__ proj_w,
                               const float* __restrict__ w_ih0) {
    __shared__ float sPW[32][32];
    __shared__ float sWI[32][33];
    int tx = threadIdx.x, ty = threadIdx.y;
    int d0 = blockIdx.x * 32, g0 = blockIdx.y * 32;
    float acc = 0.f;
    for (int p0 = 0; p0 < DP; p0 += 32) {
        sPW[ty][tx] = proj_w[(size_t)(p0 + ty) * DIN + d0 + tx];
        sWI[ty][tx] = w_ih0[(size_t)(g0 + ty) * DP + p0 + tx];
        __syncthreads();
#pragma unroll
        for (int p = 0; p < 32; p++) acc += sPW[p][tx] * sWI[ty][p];
        __syncthreads();
    }
    g_wc[(size_t)(d0 + tx) * G4 + g0 + ty] = to_tf32(acc);
}

// one block per gate row, 64-thread reduction
__global__ void bias0_kernel(const float* __restrict__ proj_b,
                             const float* __restrict__ w_ih0,
                             const float* __restrict__ b_ih0,
                             const float* __restrict__ b_hh0) {
    __shared__ float red[64];
    int g = blockIdx.x;
    const float* wr = w_ih0 + (size_t)g * DP;
    float acc = 0.f;
    for (int p = threadIdx.x; p < DP; p += 64) acc += proj_b[p] * wr[p];
    red[threadIdx.x] = acc;
    __syncthreads();
    if (threadIdx.x < 32) {
        float s = red[threadIdx.x] + red[threadIdx.x + 32];
#pragma unroll
        for (int o = 16; o > 0; o >>= 1) s += __shfl_down_sync(0xffffffffu, s, o);
        if (threadIdx.x == 0) g_bias0[g] = b_ih0[g] + b_hh0[g] + s;
    }
}

// ---------------------------------------------------------------------------
// Kernel 2: layer-0 preactivations via tf32 tensor cores (R16, unchanged).
// ---------------------------------------------------------------------------
#define APAD0 68
#define BPAD0 72
__global__ void __launch_bounds__(256)
xpre0_kernel(const float* __restrict__ in) {
    __shared__ __align__(16) float buf[128 * APAD0 + 64 * BPAD0];
    float* sAp = buf;                     // [128][APAD0]
    float* sWp = buf + 128 * APAD0;       // [64][BPAD0]
    float* sT  = buf;                     // epilogue alias [64][132]

    int tid  = threadIdx.x;
    int wid  = tid >> 5, lane = tid & 31;
    int gid  = lane >> 2, tig = lane & 3;
    int wm   = wid >> 1, wn = wid & 1;
    int t0 = blockIdx.x * 128;
    int n0 = blockIdx.y * 64;
    int b  = blockIdx.z;

    const float* inb = in + (size_t)b * SEQ * CIN;
    int base = t0 * CIN;

    float acc[2][4][4];
#pragma unroll
    for (int mi = 0; mi < 2; mi++)
#pragma unroll
        for (int ni = 0; ni < 4; ni++)
#pragma unroll
            for (int e = 0; e < 4; e++) acc[mi][ni][e] = 0.f;

    for (int kc = 0; kc < 10; kc++) {
#pragma unroll
        for (int r = 0; r < 8; r++) {
            int j = tid + r * 256;          // 2048 float4
            int t = j >> 4, k4 = (j & 15) << 2;
            int gi = base + t * CIN + kc * 64 + k4;
            float4 v = make_float4(0.f, 0.f, 0.f, 0.f);
            if (gi + 4 <= SEQ * CIN) v = *(const float4*)&inb[gi];
            v.x = to_tf32(v.x); v.y = to_tf32(v.y);
            v.z = to_tf32(v.z); v.w = to_tf32(v.w);
            *(float4*)&sAp[t * APAD0 + k4] = v;
        }
#pragma unroll
        for (int r = 0; r < 4; r++) {
            int j = tid + r * 256;          // 1024 float4
            int k = j >> 4, g4 = (j & 15) << 2;
            *(float4*)&sWp[k * BPAD0 + g4] =
                *(const float4*)&g_wc[(size_t)(kc * 64 + k) * G4 + n0 + g4];
        }
        __syncthreads();

#pragma unroll
        for (int ki = 0; ki < 8; ki++) {
            unsigned afr[2][4];
#pragma unroll
            for (int mi = 0; mi < 2; mi++) {
                const float* ar = sAp + (wm * 32 + mi * 16 + gid) * APAD0 + ki * 8 + tig;
                afr[mi][0] = __float_as_uint(ar[0]);
                afr[mi][1] = __float_as_uint(ar[8 * APAD0]);
                afr[mi][2] = __float_as_uint(ar[4]);
                afr[mi][3] = __float_as_uint(ar[8 * APAD0 + 4]);
            }
            unsigned bfr[4][2];
#pragma unroll
            for (int ni = 0; ni < 4; ni++) {
                const float* br = sWp + (ki * 8 + tig) * BPAD0 + wn * 32 + ni * 8 + gid;
                bfr[ni][0] = __float_as_uint(br[0]);
                bfr[ni][1] = __float_as_uint(br[4 * BPAD0]);
            }
#pragma unroll
            for (int mi = 0; mi < 2; mi++)
#pragma unroll
                for (int ni = 0; ni < 4; ni++)
                    mma_tf32(acc[mi][ni], afr[mi], bfr[ni]);
        }
        __syncthreads();
    }

#pragma unroll
    for (int mi = 0; mi < 2; mi++)
#pragma unroll
        for (int ni = 0; ni < 4; ni++) {
            int tl = wm * 32 + mi * 16 + gid;
            int gl = wn * 32 + ni * 8 + tig * 2;
            sT[gl * 132 + tl]           = acc[mi][ni][0];
            sT[(gl + 1) * 132 + tl]     = acc[mi][ni][1];
            sT[gl * 132 + tl + 8]       = acc[mi][ni][2];
            sT[(gl + 1) * 132 + tl + 8] = acc[mi][ni][3];
        }
    __syncthreads();
#pragma unroll
    for (int r = 0; r < 8; r++) {
        int j = tid + r * 256;              // 2048 float4
        int g = j >> 5, t4 = (j & 31) << 2;
        if (t0 + t4 + 4 <= XT) {
            float4 v = *(float4*)&sT[g * 132 + t4];
            float bv = g_bias0[n0 + g];
            v.x += bv; v.y += bv; v.z += bv; v.w += bv;
            *(float4*)&g_xpre[((size_t)b * G4 + n0 + g) * XT + t0 + t4] = v;
        }
    }
}

// ---------------------------------------------------------------------------
// Kernel 3: input preactivations for layers 1..3 via tf32.
// R17: rebuilt as a clone of the proven xpre0 structure — BM=128, BN=64,
// K=128 in 2 chunks of 64, identical warp layout / fragments / epilogue.
// Halves CTA count (16384 -> 8192) and B-staging redundancy. A staged from
// g_hseq (tf32-rounded, bounds-guarded); B transposed-staged from w_ih.
// ---------------------------------------------------------------------------
__global__ void __launch_bounds__(256)
gemm_ih_kernel(const float* __restrict__ w_ih,
               const float* __restrict__ b_ih,
               const float* __restrict__ b_hh) {
    __shared__ __align__(16) float buf[128 * APAD0 + 64 * BPAD0];
    float* sAp = buf;                     // [128][APAD0]
    float* sWp = buf + 128 * APAD0;       // [64][BPAD0]
    float* sT  = buf;                     // epilogue alias [64][132]

    int tid  = threadIdx.x;
    int wid  = tid >> 5, lane = tid & 31;
    int gid  = lane >> 2, tig = lane & 3;
    int wm   = wid >> 1, wn = wid & 1;
    int n0 = blockIdx.x * 64;             // n-block on x for L2 reuse of A
    int t0 = blockIdx.y * 128;
    int b  = blockIdx.z;

    float acc[2][4][4];
#pragma unroll
    for (int mi = 0; mi < 2; mi++)
#pragma unroll
        for (int ni = 0; ni < 4; ni++)
#pragma unroll
            for (int e = 0; e < 4; e++) acc[mi][ni][e] = 0.f;

    for (int kc = 0; kc < 2; kc++) {
        // stage A: sAp[t][kk] = tf32(hseq[b][t0+t][kc*64+kk])
#pragma unroll
        for (int r = 0; r < 8; r++) {
            int j = tid + r * 256;          // 2048 float4
            int t = j >> 4, k4 = (j & 15) << 2;
            float4 v = make_float4(0.f, 0.f, 0.f, 0.f);
            if (t0 + t < L_OUT)
                v = *(const float4*)&g_hseq[((size_t)b * L_OUT + t0 + t) * HID
                                            + kc * 64 + k4];
            v.x = to_tf32(v.x); v.y = to_tf32(v.y);
            v.z = to_tf32(v.z); v.w = to_tf32(v.w);
            *(float4*)&sAp[t * APAD0 + k4] = v;
        }
        // stage B transposed: sWp[k][g] = tf32(w_ih[n0+g][kc*64+k])
#pragma unroll
        for (int r = 0; r < 4; r++) {
            int j = tid + r * 256;          // 1024 groups (g, k-quad)
            int g = j & 63, kq = j >> 6;
            int k4 = kq << 2;
            float4 v = *(const float4*)&w_ih[(size_t)(n0 + g) * HID + kc * 64 + k4];
            sWp[(k4 + 0) * BPAD0 + g] = to_tf32(v.x);
            sWp[(k4 + 1) * BPAD0 + g] = to_tf32(v.y);
            sWp[(k4 + 2) * BPAD0 + g] = to_tf32(v.z);
            sWp[(k4 + 3) * BPAD0 + g] = to_tf32(v.w);
        }
        __syncthreads();

#pragma unroll
        for (int ki = 0; ki < 8; ki++) {
            unsigned afr[2][4];
#pragma unroll
            for (int mi = 0; mi < 2; mi++) {
                const float* ar = sAp + (wm * 32 + mi * 16 + gid) * APAD0 + ki * 8 + tig;
                afr[mi][0] = __float_as_uint(ar[0]);
                afr[mi][1] = __float_as_uint(ar[8 * APAD0]);
                afr[mi][2] = __float_as_uint(ar[4]);
                afr[mi][3] = __float_as_uint(ar[8 * APAD0 + 4]);
            }
            unsigned bfr[4][2];
#pragma unroll
            for (int ni = 0; ni < 4; ni++) {
                const float* br = sWp + (ki * 8 + tig) * BPAD0 + wn * 32 + ni * 8 + gid;
                bfr[ni][0] = __float_as_uint(br[0]);
                bfr[ni][1] = __float_as_uint(br[4 * BPAD0]);
            }
#pragma unroll
            for (int mi = 0; mi < 2; mi++)
#pragma unroll
                for (int ni = 0; ni < 4; ni++)
                    mma_tf32(acc[mi][ni], afr[mi], bfr[ni]);
        }
        __syncthreads();
    }

    // epilogue: transpose to sT[g][t] (pad 132), coalesced stores + bias
#pragma unroll
    for (int mi = 0; mi < 2; mi++)
#pragma unroll
        for (int ni = 0; ni < 4; ni++) {
            int tl = wm * 32 + mi * 16 + gid;
            int gl = wn * 32 + ni * 8 + tig * 2;
            sT[gl * 132 + tl]           = acc[mi][ni][0];
            sT[(gl + 1) * 132 + tl]     = acc[mi][ni][1];
            sT[gl * 132 + tl + 8]       = acc[mi][ni][2];
            sT[(gl + 1) * 132 + tl + 8] = acc[mi][ni][3];
        }
    __syncthreads();
#pragma unroll
    for (int r = 0; r < 8; r++) {
        int j = tid + r * 256;              // 2048 float4
        int g = j >> 5, t4 = (j & 31) << 2;
        if (t0 + t4 + 4 <= XT) {
            float4 v = *(float4*)&sT[g * 132 + t4];
            float bv = b_ih[n0 + g] + b_hh[n0 + g];
            v.x += bv; v.y += bv; v.z += bv; v.w += bv;
            *(float4*)&g_xpre[((size_t)b * G4 + n0 + g) * XT + t0 + t4] = v;
        }
    }
}

// ---------------------------------------------------------------------------
// Kernel 4: recurrent scan — bitwise R15/R16 protocol (measured best).
// R17: store_h flag — final layer stores g_hseq only at t = L_OUT-1.
// ---------------------------------------------------------------------------
__global__ void __cluster_dims__(2, 1, 1) __launch_bounds__(256, 1)
scan_kernel(const float* __restrict__ w_hh, int store_h) {
    __shared__ __align__(16) float hbuf[2][64];
    __shared__ __align__(16) float land[2][64];
    __shared__ __align__(8) unsigned long long mbars[2];

    int tid  = threadIdx.x;
    int rank = blockIdx.x & 1;
    int b    = blockIdx.x >> 1;
    int gate = tid & 3;
    int ul   = tid >> 2;
    int ug   = rank * 64 + ul;
    int row  = gate * HID + ug;
    int kown  = rank * 64;
    int kpeer = (rank ^ 1) * 64;

    unsigned long long wown[32], wpeer[32];
    {
        const ulonglong2* wr = (const ulonglong2*)(w_hh + (size_t)row * HID + kown);
#pragma unroll
        for (int k = 0; k < 16; k++) {
            ulonglong2 u = wr[k];
            wown[2 * k]     = u.x;
            wown[2 * k + 1] = u.y;
        }
        const ulonglong2* wp = (const ulonglong2*)(w_hh + (size_t)row * HID + kpeer);
#pragma unroll
        for (int k = 0; k < 16; k++) {
            ulonglong2 u = wp[k];
            wpeer[2 * k]     = u.x;
            wpeer[2 * k + 1] = u.y;
        }
    }

    if (tid < 64) {
        hbuf[0][tid] = 0.f; hbuf[1][tid] = 0.f;
        land[0][tid] = 0.f; land[1][tid] = 0.f;
    }
    unsigned bar0 = smem_u32(&mbars[0]);
    unsigned bar1 = smem_u32(&mbars[1]);
    if (tid == 0) { mbar_init(bar0, 1); mbar_init(bar1, 1); }
    __syncthreads();
    cluster_barrier();

    unsigned peer = rank ^ 1;
    unsigned peer_l0 = mapa_rank(smem_u32(&land[0][0]), peer) + (unsigned)ul * 4u;
    unsigned peer_l1 = mapa_rank(smem_u32(&land[1][0]), peer) + (unsigned)ul * 4u;
    unsigned peer_b0 = mapa_rank(bar0, peer);
    unsigned peer_b1 = mapa_rank(bar1, peer);

    float c = 0.f;
    const size_t hrow = (size_t)b * L_OUT;
    const float* xrow_p = g_xpre + ((size_t)b * G4 + row) * XT;

    const float A_ = (gate == 2) ? 1.f : 0.5f;
    const float B_ = (gate == 2) ? 1.f : 0.5f;
    const float C_ = (gate == 2) ? 0.f : 0.5f;
    const bool  tail   = (gate == 0);
    const bool  sender = tail && ((ul & 1) == 0);

    float4 xcur = *(const float4*)(xrow_p);

    for (int t4 = 0; t4 < L_OUT; t4 += 4) {
        float4 xnxt = *(const float4*)(xrow_p + t4 + 4);

#pragma unroll
        for (int s = 0; s < 4; s++) {
            int t = t4 + s;
            float xp = (s == 0) ? xcur.x : (s == 1) ? xcur.y : (s == 2) ? xcur.z : xcur.w;

            if (tid == 0 && t + 1 < L_OUT)
                mbar_expect_tx((t & 1) ? bar1 : bar0, 256);

            unsigned long long a0 = pk2(xp, 0.f), a1 = pk2(0.f, 0.f);
            unsigned long long a2 = pk2(0.f, 0.f), a3 = pk2(0.f, 0.f);
            {
                const ulonglong2* h2 = (const ulonglong2*)hbuf[(t + 1) & 1];
#pragma unroll
                for (int k = 0; k < 8; k++) {
                    ulonglong2 u = h2[2 * k];
                    ulonglong2 v = h2[2 * k + 1];
                    fma2(a0, wown[4 * k],     u.x);
                    fma2(a1, wown[4 * k + 1], u.y);
                    fma2(a2, wown[4 * k + 2], v.x);
                    fma2(a3, wown[4 * k + 3], v.y);
                }
            }

            if (t > 0) {
                int pv = t - 1;
                mbar_wait_cluster((pv & 1) ? bar1 : bar0, (unsigned)((pv >> 1) & 1));
            }

            {
                const ulonglong2* h2 = (const ulonglong2*)land[(t + 1) & 1];
#pragma unroll
                for (int k = 0; k < 8; k++) {
                    ulonglong2 u = h2[2 * k];
                    ulonglong2 v = h2[2 * k + 1];
                    fma2(a0, wpeer[4 * k],     u.x);
                    fma2(a1, wpeer[4 * k + 1], u.y);
                    fma2(a2, wpeer[4 * k + 2], v.x);
                    fma2(a3, wpeer[4 * k + 3], v.y);
                }
            }

            float2 q = unpk2(add2(add2(a0, a1), add2(a2, a3)));
            float pre = q.x + q.y;
            float act = fmaf(A_, tanhf_fast(B_ * pre), C_);

            float fv = __shfl_down_sync(0xffffffffu, act, 1);
            float gv = __shfl_down_sync(0xffffffffu, act, 2);
            float ov = __shfl_down_sync(0xffffffffu, act, 3);

            float h = 0.f;
            if (tail) {
                c = fmaf(fv, c, act * gv);
                h = ov * tanhf_fast(c);
            }
            float hp = __shfl_down_sync(0xffffffffu, h, 4);
            if (tail) {
                if (sender && t + 1 < L_OUT)
                    st_async_f32x2((t & 1) ? peer_l1 : peer_l0, h, hp,
                                   (t & 1) ? peer_b1 : peer_b0);
                if (store_h || t == L_OUT - 1)
                    g_hseq[(hrow + t) * HID + ug] = h;
                hbuf[t & 1][ul] = h;
            }
            __syncthreads();
        }
        xcur = xnxt;
    }
    cluster_barrier();
}

// ---------------------------------------------------------------------------
// Kernel 5: readout.
// ---------------------------------------------------------------------------
__global__ void out_kernel(const float* __restrict__ out_w,
                           const float* __restrict__ out_b,
                           float* __restrict__ out) {
    __shared__ float h[HID];
    int b = blockIdx.x;
    if (threadIdx.x < HID)
        h[threadIdx.x] = g_hseq[((size_t)b * L_OUT + (L_OUT - 1)) * HID + threadIdx.x];
    __syncthreads();
    if (threadIdx.x < LBL) {
        float acc = out_b[threadIdx.x];
        const float* wr = out_w + (size_t)threadIdx.x * HID;
#pragma unroll 8
        for (int k = 0; k < HID; k++) acc += wr[k] * h[k];
        out[(size_t)b * LBL + threadIdx.x] = acc;
    }
}

// ---------------------------------------------------------------------------
// Launch
// ---------------------------------------------------------------------------
extern "C" void kernel_launch(void* const* d_in, const int* in_sizes, int n_in,
                              void* d_out, int out_size) {
    const float* inputs    = (const float*)d_in[0];
    const float* proj_w    = (const float*)d_in[4];
    const float* proj_b    = (const float*)d_in[5];
    const float* w_ih0     = (const float*)d_in[6];
    const float* w_hh0     = (const float*)d_in[7];
    const float* b_ih0     = (const float*)d_in[8];
    const float* b_hh0     = (const float*)d_in[9];
    const float* w_ih_rest = (const float*)d_in[10];
    const float* w_hh_rest = (const float*)d_in[11];
    const float* b_ih_rest = (const float*)d_in[12];
    const float* b_hh_rest = (const float*)d_in[13];
    const float* out_w     = (const float*)d_in[14];
    const float* out_b     = (const float*)d_in[15];
    float* out = (float*)d_out;

    combine_kernel<<<dim3(DIN / 32, G4 / 32), dim3(32, 32)>>>(proj_w, w_ih0);
    bias0_kernel<<<G4, 64>>>(proj_b, w_ih0, b_ih0, b_hh0);

    xpre0_kernel<<<dim3((L_OUT + 127) / 128, G4 / 64, BATCH), 256>>>(inputs);

    scan_kernel<<<BATCH * 2, 256>>>(w_hh0, 1);

    for (int l = 0; l < 3; l++) {
        gemm_ih_kernel<<<dim3(G4 / 64, (L_OUT + 127) / 128, BATCH), 256>>>(
            w_ih_rest + (size_t)l * G4 * HID,
            b_ih_rest + (size_t)l * G4,
            b_hh_rest + (size_t)l * G4);
        scan_kernel<<<BATCH * 2, 256>>>(w_hh_rest + (size_t)l * G4 * HID,
                                        (l < 2) ? 1 : 0);
    }

    out_kernel<<<BATCH, 128>>>(out_w, out_b, out);
}